// round 1
// baseline (speedup 1.0000x reference)
#include <cuda_runtime.h>
#include <math.h>

// Problem constants
constexpr int Bc = 2;
constexpr int Sc = 2048;
constexpr int Ec = 1024;
constexpr int Hc = 16;
constexpr int HDc = 64;
constexpr int Mc = Bc * Sc;        // 4096
constexpr int E3 = 3 * Ec;         // 3072

// Scratch (no cudaMalloc allowed)
__device__ float g_qkv[Mc * E3];       // [M, 3E]  ~50 MB
__device__ float g_attn[Mc * Ec];      // [M, E]   ~17 MB

// ---------------------------------------------------------------------------
// GEMM:  C[M,N] = A[M,K] @ W[N,K]^T + bias[N]
// Tiles: 128x128x8, 256 threads, 8x8 microtile per thread.
// ---------------------------------------------------------------------------
constexpr int GBM = 128, GBN = 128, GBK = 8;

__global__ __launch_bounds__(256)
void gemm_bias_kernel(const float* __restrict__ A, const float* __restrict__ W,
                      const float* __restrict__ bias, float* __restrict__ C,
                      int M, int N, int K)
{
    __shared__ float As[GBK][GBM + 4];   // pad 4 -> conflict-free transposed STS, broadcast LDS
    __shared__ float Bs[GBK][GBN];       // unpadded -> float4 LDS conflict-free

    int tid = threadIdx.x;
    int tx = tid & 15;        // 0..15 (N direction)
    int ty = tid >> 4;        // 0..15 (M direction)
    int bm = blockIdx.y * GBM;
    int bn = blockIdx.x * GBN;

    int lk = tid & 7;         // 0..7  (k within tile)
    int lr = tid >> 3;        // 0..31 (row within tile)

    const float* Ag = A + (size_t)(bm + lr) * K + lk;
    const float* Wg = W + (size_t)(bn + lr) * K + lk;

    float acc[8][8] = {};

    for (int k0 = 0; k0 < K; k0 += GBK) {
        #pragma unroll
        for (int i = 0; i < 4; i++) {
            As[lk][lr + 32 * i] = Ag[(size_t)(32 * i) * K + k0];
            Bs[lk][lr + 32 * i] = Wg[(size_t)(32 * i) * K + k0];
        }
        __syncthreads();

        #pragma unroll
        for (int k = 0; k < GBK; k++) {
            float a[8];
            #pragma unroll
            for (int i = 0; i < 8; i++) a[i] = As[k][ty * 8 + i];
            float4 b0 = *(const float4*)&Bs[k][tx * 8];
            float4 b1 = *(const float4*)&Bs[k][tx * 8 + 4];
            float b[8] = {b0.x, b0.y, b0.z, b0.w, b1.x, b1.y, b1.z, b1.w};
            #pragma unroll
            for (int i = 0; i < 8; i++)
                #pragma unroll
                for (int j = 0; j < 8; j++)
                    acc[i][j] += a[i] * b[j];
        }
        __syncthreads();
    }

    // Epilogue: add bias, vectorized stores
    float bb[8];
    #pragma unroll
    for (int j = 0; j < 8; j++) bb[j] = bias[bn + tx * 8 + j];

    #pragma unroll
    for (int i = 0; i < 8; i++) {
        int row = bm + ty * 8 + i;
        float4 v0 = make_float4(acc[i][0] + bb[0], acc[i][1] + bb[1],
                                acc[i][2] + bb[2], acc[i][3] + bb[3]);
        float4 v1 = make_float4(acc[i][4] + bb[4], acc[i][5] + bb[5],
                                acc[i][6] + bb[6], acc[i][7] + bb[7]);
        float* cp = C + (size_t)row * N + bn + tx * 8;
        *(float4*)(cp)     = v0;
        *(float4*)(cp + 4) = v1;
    }
}

// ---------------------------------------------------------------------------
// Flash attention (causal), fp32. One CTA = one (b, h, q-tile of 64 rows).
// Online softmax over 64-wide key tiles. HD = 64.
// Shared: Qs/Ks/Vs/Ps each [64][65] (pad 1 for bank spread) = 66560 B dynamic.
// ---------------------------------------------------------------------------
constexpr int FT = 64;      // tile size (q rows, k cols, head dim)
constexpr int FLD = 65;     // padded leading dim

__global__ __launch_bounds__(256)
void flash_kernel(const float* __restrict__ qkv, float* __restrict__ attn_out)
{
    extern __shared__ float sm[];
    float* Qs = sm;                  // [64][65]
    float* Ks = sm + FT * FLD;       // [64][65]
    float* Vs = sm + 2 * FT * FLD;   // [64][65]
    float* Ps = sm + 3 * FT * FLD;   // [64][65]

    int tid = threadIdx.x;
    int tx = tid & 15;     // key-col / headdim-col group
    int ty = tid >> 4;     // q-row group
    int qt = blockIdx.x;   // q tile index (0..31)
    int h  = blockIdx.y;
    int b  = blockIdx.z;
    int q0 = qt * FT;

    // Load Q tile: Qs[r][d] = qkv[(b*S + q0+r)][0*E + h*64 + d]
    {
        int d  = tid & 63;
        int r0 = tid >> 6;           // 0..3
        #pragma unroll 4
        for (int i = 0; i < 16; i++) {
            int r = r0 + 4 * i;
            Qs[r * FLD + d] = qkv[(size_t)(b * Sc + q0 + r) * E3 + h * HDc + d];
        }
    }

    float o[4][4] = {};
    float mrow[4] = {-1e30f, -1e30f, -1e30f, -1e30f};
    float lrow[4] = {};

    for (int kt = 0; kt <= qt; kt++) {
        __syncthreads();   // protect Ks/Vs/Ps from previous iteration readers
        int kc0 = kt * FT;
        {
            int d  = tid & 63;
            int r0 = tid >> 6;
            #pragma unroll 4
            for (int i = 0; i < 16; i++) {
                int r = r0 + 4 * i;
                size_t base = (size_t)(b * Sc + kc0 + r) * E3 + h * HDc + d;
                Ks[r * FLD + d] = qkv[base + Ec];       // K
                Vs[r * FLD + d] = qkv[base + 2 * Ec];   // V
            }
        }
        __syncthreads();

        // S = Q @ K^T  (scaled)
        float s[4][4] = {};
        #pragma unroll 8
        for (int d = 0; d < FT; d++) {
            float qv[4], kv[4];
            #pragma unroll
            for (int i = 0; i < 4; i++) qv[i] = Qs[(ty * 4 + i) * FLD + d];
            #pragma unroll
            for (int j = 0; j < 4; j++) kv[j] = Ks[(tx * 4 + j) * FLD + d];
            #pragma unroll
            for (int i = 0; i < 4; i++)
                #pragma unroll
                for (int j = 0; j < 4; j++)
                    s[i][j] += qv[i] * kv[j];
        }
        #pragma unroll
        for (int i = 0; i < 4; i++)
            #pragma unroll
            for (int j = 0; j < 4; j++)
                s[i][j] *= 0.125f;   // 1/sqrt(64)

        // Causal mask (only relevant on the diagonal tile)
        if (kt == qt) {
            #pragma unroll
            for (int i = 0; i < 4; i++)
                #pragma unroll
                for (int j = 0; j < 4; j++)
                    if (tx * 4 + j > ty * 4 + i) s[i][j] = -1e30f;
        }

        // Online softmax update (row stats across 16 lanes sharing each row)
        #pragma unroll
        for (int i = 0; i < 4; i++) {
            float tm = fmaxf(fmaxf(s[i][0], s[i][1]), fmaxf(s[i][2], s[i][3]));
            #pragma unroll
            for (int off = 8; off >= 1; off >>= 1)
                tm = fmaxf(tm, __shfl_xor_sync(0xffffffffu, tm, off));
            float mn = fmaxf(mrow[i], tm);
            float corr = __expf(mrow[i] - mn);
            float rs = 0.f;
            #pragma unroll
            for (int j = 0; j < 4; j++) {
                s[i][j] = __expf(s[i][j] - mn);
                rs += s[i][j];
            }
            #pragma unroll
            for (int off = 8; off >= 1; off >>= 1)
                rs += __shfl_xor_sync(0xffffffffu, rs, off);
            lrow[i] = lrow[i] * corr + rs;
            mrow[i] = mn;
            #pragma unroll
            for (int j = 0; j < 4; j++) o[i][j] *= corr;
        }

        // Stage P to shared for the P@V GEMM (thread col-ownership changes)
        #pragma unroll
        for (int i = 0; i < 4; i++)
            #pragma unroll
            for (int j = 0; j < 4; j++)
                Ps[(ty * 4 + i) * FLD + tx * 4 + j] = s[i][j];
        __syncthreads();

        // O += P @ V  (thread owns rows ty*4+i, headdim cols tx*4+j)
        #pragma unroll 8
        for (int c = 0; c < FT; c++) {
            float pv[4], vv[4];
            #pragma unroll
            for (int i = 0; i < 4; i++) pv[i] = Ps[(ty * 4 + i) * FLD + c];
            #pragma unroll
            for (int j = 0; j < 4; j++) vv[j] = Vs[c * FLD + tx * 4 + j];
            #pragma unroll
            for (int i = 0; i < 4; i++)
                #pragma unroll
                for (int j = 0; j < 4; j++)
                    o[i][j] += pv[i] * vv[j];
        }
    }

    // Epilogue: normalize, write attn_out[b][s][h*64 + d]
    #pragma unroll
    for (int i = 0; i < 4; i++) {
        float inv = 1.0f / lrow[i];
        int r = q0 + ty * 4 + i;
        float* op = g_attn + (size_t)(b * Sc + r) * Ec + h * HDc + tx * 4;
        #pragma unroll
        for (int j = 0; j < 4; j++) op[j] = o[i][j] * inv;
    }
    (void)attn_out;
}

// ---------------------------------------------------------------------------
extern "C" void kernel_launch(void* const* d_in, const int* in_sizes, int n_in,
                              void* d_out, int out_size)
{
    const float* x      = (const float*)d_in[0];
    const float* qkv_w  = (const float*)d_in[1];
    const float* qkv_b  = (const float*)d_in[2];
    const float* out_w  = (const float*)d_in[3];
    const float* out_b  = (const float*)d_in[4];
    float* out = (float*)d_out;

    float* qkvp;
    float* attnp;
    cudaGetSymbolAddress((void**)&qkvp, g_qkv);
    cudaGetSymbolAddress((void**)&attnp, g_attn);

    constexpr int FLASH_SMEM = 4 * FT * FLD * (int)sizeof(float);  // 66560 B
    cudaFuncSetAttribute(flash_kernel,
                         cudaFuncAttributeMaxDynamicSharedMemorySize, FLASH_SMEM);

    // 1) QKV projection: [4096,1024] @ [3072,1024]^T + b -> g_qkv [4096,3072]
    dim3 g1(E3 / GBN, Mc / GBM);   // (24, 32)
    gemm_bias_kernel<<<g1, 256>>>(x, qkv_w, qkv_b, qkvp, Mc, E3, Ec);

    // 2) Causal flash attention -> g_attn [4096,1024] (already [B,S,E] layout)
    dim3 g2(Sc / FT, Hc, Bc);      // (32, 16, 2)
    flash_kernel<<<g2, 256, FLASH_SMEM>>>(qkvp, attnp);

    // 3) Output projection: [4096,1024] @ [1024,1024]^T + b -> d_out
    dim3 g3(Ec / GBN, Mc / GBM);   // (8, 32)
    gemm_bias_kernel<<<g3, 256>>>(attnp, out_w, out_b, out, Mc, Ec, Ec);
}

// round 3
// speedup vs baseline: 1.6075x; 1.6075x over previous
#include <cuda_runtime.h>
#include <cuda_bf16.h>
#include <cstdint>
#include <math.h>

// ===========================================================================
// Problem constants
// ===========================================================================
constexpr int Bc = 2;
constexpr int Sc = 2048;
constexpr int Ec = 1024;
constexpr int Hc = 16;
constexpr int HDc = 64;
constexpr int Mc = Bc * Sc;        // 4096
constexpr int E3 = 3 * Ec;         // 3072

// Scratch (no cudaMalloc allowed)
__device__ float g_qkv[Mc * E3];       // [M, 3E]
__device__ float g_attn[Mc * Ec];      // [M, E]

// ===========================================================================
// mma.sync bf16 GEMM:  C[M,N] = A[M,K] @ W[N,K]^T + bias[N]
// Split-bf16 3-pass (Ah*Bh + Ah*Bl + Al*Bh), fp32 register accumulators.
// CTA tile 128x128, 8 warps (2M x 4N), warp tile 64x32, K-chunk 32.
// ===========================================================================
constexpr int CHK = 32;            // K per chunk (bf16)
constexpr int LDT = 40;            // padded smem leading dim (bf16 elems; 80B row)

__device__ __forceinline__ uint32_t pack_bf16x2(__nv_bfloat16 lo, __nv_bfloat16 hi) {
    __nv_bfloat162 t = __halves2bfloat162(lo, hi);   // .x = lo (low 16 bits)
    return *reinterpret_cast<uint32_t*>(&t);
}

// Convert 8 fp32 -> 8 bf16 hi + 8 bf16 lo, store as uint4 into padded tiles.
__device__ __forceinline__ void cvt_store(
    __nv_bfloat16* __restrict__ hit, __nv_bfloat16* __restrict__ lot,
    int row, int seg, const float* __restrict__ g)
{
    float4 a0 = *reinterpret_cast<const float4*>(g);
    float4 a1 = *reinterpret_cast<const float4*>(g + 4);
    float v[8] = {a0.x, a0.y, a0.z, a0.w, a1.x, a1.y, a1.z, a1.w};
    uint32_t hv[4], lv[4];
    #pragma unroll
    for (int j = 0; j < 4; j++) {
        __nv_bfloat16 h0 = __float2bfloat16(v[2*j]);
        __nv_bfloat16 h1 = __float2bfloat16(v[2*j+1]);
        float r0 = v[2*j]   - __bfloat162float(h0);
        float r1 = v[2*j+1] - __bfloat162float(h1);
        hv[j] = pack_bf16x2(h0, h1);
        lv[j] = pack_bf16x2(__float2bfloat16(r0), __float2bfloat16(r1));
    }
    *reinterpret_cast<uint4*>(hit + row * LDT + seg) = make_uint4(hv[0], hv[1], hv[2], hv[3]);
    *reinterpret_cast<uint4*>(lot + row * LDT + seg) = make_uint4(lv[0], lv[1], lv[2], lv[3]);
}

__device__ __forceinline__ uint32_t smem_u32(const void* p) {
    return (uint32_t)__cvta_generic_to_shared(p);
}

__device__ __forceinline__ void ldm_x4(uint32_t addr, uint32_t r[4]) {
    asm volatile("ldmatrix.sync.aligned.m8n8.x4.shared.b16 {%0,%1,%2,%3}, [%4];"
        : "=r"(r[0]), "=r"(r[1]), "=r"(r[2]), "=r"(r[3]) : "r"(addr));
}

__device__ __forceinline__ void mma_bf16(float c[4], const uint32_t a[4],
                                         uint32_t b0, uint32_t b1) {
    asm volatile(
        "mma.sync.aligned.m16n8k16.row.col.f32.bf16.bf16.f32 "
        "{%0,%1,%2,%3}, {%4,%5,%6,%7}, {%8,%9}, {%0,%1,%2,%3};"
        : "+f"(c[0]), "+f"(c[1]), "+f"(c[2]), "+f"(c[3])
        : "r"(a[0]), "r"(a[1]), "r"(a[2]), "r"(a[3]), "r"(b0), "r"(b1));
}

__global__ __launch_bounds__(256, 2)
void gemm_mma_kernel(const float* __restrict__ A, const float* __restrict__ W,
                     const float* __restrict__ bias, float* __restrict__ C,
                     int M, int N, int K)
{
    __shared__ __align__(16) __nv_bfloat16 Ah[128 * LDT];
    __shared__ __align__(16) __nv_bfloat16 Al[128 * LDT];
    __shared__ __align__(16) __nv_bfloat16 Bh[128 * LDT];
    __shared__ __align__(16) __nv_bfloat16 Bl[128 * LDT];

    int tid  = threadIdx.x;
    int lane = tid & 31;
    int wid  = tid >> 5;
    int wm   = wid >> 2;       // 0..1 (M)
    int wn   = wid & 3;        // 0..3 (N)
    int bm   = blockIdx.y * 128;
    int bn   = blockIdx.x * 128;

    float acc[4][4][4] = {};   // [mt][n8][frag]

    // ldmatrix lane addressing: row = lane&15, k-half = lane>>4
    int lrow  = lane & 15;
    int lhalf = (lane >> 4) * 8;

    for (int k0 = 0; k0 < K; k0 += CHK) {
        __syncthreads();   // previous chunk's reads done before overwrite

        // ---- load + split-convert A(128x32) and B(128x32) ----
        #pragma unroll
        for (int i = 0; i < 2; i++) {
            int s   = tid + 256 * i;     // 0..511
            int row = s >> 2;            // 0..127
            int seg = (s & 3) * 8;       // 0,8,16,24
            cvt_store(Ah, Al, row, seg, A + (size_t)(bm + row) * K + k0 + seg);
            cvt_store(Bh, Bl, row, seg, W + (size_t)(bn + row) * K + k0 + seg);
        }
        __syncthreads();

        // ---- 2 k-steps of 16 ----
        #pragma unroll
        for (int ks = 0; ks < 2; ks++) {
            int kk = ks * 16 + lhalf;

            uint32_t af[4][4];   // A-hi frags, 4 m-tiles
            uint32_t bhf[2][4];  // B-hi frags, 2 n16-tiles
            #pragma unroll
            for (int mt = 0; mt < 4; mt++)
                ldm_x4(smem_u32(Ah + (wm * 64 + mt * 16 + lrow) * LDT + kk), af[mt]);
            #pragma unroll
            for (int nt = 0; nt < 2; nt++)
                ldm_x4(smem_u32(Bh + (wn * 32 + nt * 16 + lrow) * LDT + kk), bhf[nt]);

            // pass 1: Ah * Bh
            #pragma unroll
            for (int mt = 0; mt < 4; mt++)
                #pragma unroll
                for (int nt = 0; nt < 2; nt++) {
                    mma_bf16(acc[mt][nt*2+0], af[mt], bhf[nt][0], bhf[nt][2]);
                    mma_bf16(acc[mt][nt*2+1], af[mt], bhf[nt][1], bhf[nt][3]);
                }

            // pass 2: Ah * Bl
            uint32_t blf[2][4];
            #pragma unroll
            for (int nt = 0; nt < 2; nt++)
                ldm_x4(smem_u32(Bl + (wn * 32 + nt * 16 + lrow) * LDT + kk), blf[nt]);
            #pragma unroll
            for (int mt = 0; mt < 4; mt++)
                #pragma unroll
                for (int nt = 0; nt < 2; nt++) {
                    mma_bf16(acc[mt][nt*2+0], af[mt], blf[nt][0], blf[nt][2]);
                    mma_bf16(acc[mt][nt*2+1], af[mt], blf[nt][1], blf[nt][3]);
                }

            // pass 3: Al * Bh
            uint32_t alf[4][4];
            #pragma unroll
            for (int mt = 0; mt < 4; mt++)
                ldm_x4(smem_u32(Al + (wm * 64 + mt * 16 + lrow) * LDT + kk), alf[mt]);
            #pragma unroll
            for (int mt = 0; mt < 4; mt++)
                #pragma unroll
                for (int nt = 0; nt < 2; nt++) {
                    mma_bf16(acc[mt][nt*2+0], alf[mt], bhf[nt][0], bhf[nt][2]);
                    mma_bf16(acc[mt][nt*2+1], alf[mt], bhf[nt][1], bhf[nt][3]);
                }
        }
    }

    // ---- epilogue: bias + store (c0,c1 contiguous -> float2) ----
    #pragma unroll
    for (int mt = 0; mt < 4; mt++) {
        int r0 = bm + wm * 64 + mt * 16 + (lane >> 2);
        #pragma unroll
        for (int n8 = 0; n8 < 4; n8++) {
            int col = bn + wn * 32 + n8 * 8 + (lane & 3) * 2;
            float b0 = bias[col], b1 = bias[col + 1];
            float2 v0 = make_float2(acc[mt][n8][0] + b0, acc[mt][n8][1] + b1);
            float2 v1 = make_float2(acc[mt][n8][2] + b0, acc[mt][n8][3] + b1);
            *reinterpret_cast<float2*>(C + (size_t)r0 * N + col) = v0;
            *reinterpret_cast<float2*>(C + (size_t)(r0 + 8) * N + col) = v1;
        }
    }
}

// ===========================================================================
// Flash attention (causal), fp32 SIMT (unchanged — next round's target)
// ===========================================================================
constexpr int FT = 64;
constexpr int FLD = 65;

__global__ __launch_bounds__(256)
void flash_kernel(const float* __restrict__ qkv, float* __restrict__ attn_out)
{
    extern __shared__ float sm[];
    float* Qs = sm;
    float* Ks = sm + FT * FLD;
    float* Vs = sm + 2 * FT * FLD;
    float* Ps = sm + 3 * FT * FLD;

    int tid = threadIdx.x;
    int tx = tid & 15;
    int ty = tid >> 4;
    int qt = blockIdx.x;
    int h  = blockIdx.y;
    int b  = blockIdx.z;
    int q0 = qt * FT;

    {
        int d  = tid & 63;
        int r0 = tid >> 6;
        #pragma unroll 4
        for (int i = 0; i < 16; i++) {
            int r = r0 + 4 * i;
            Qs[r * FLD + d] = qkv[(size_t)(b * Sc + q0 + r) * E3 + h * HDc + d];
        }
    }

    float o[4][4] = {};
    float mrow[4] = {-1e30f, -1e30f, -1e30f, -1e30f};
    float lrow[4] = {};

    for (int kt = 0; kt <= qt; kt++) {
        __syncthreads();
        int kc0 = kt * FT;
        {
            int d  = tid & 63;
            int r0 = tid >> 6;
            #pragma unroll 4
            for (int i = 0; i < 16; i++) {
                int r = r0 + 4 * i;
                size_t base = (size_t)(b * Sc + kc0 + r) * E3 + h * HDc + d;
                Ks[r * FLD + d] = qkv[base + Ec];
                Vs[r * FLD + d] = qkv[base + 2 * Ec];
            }
        }
        __syncthreads();

        float s[4][4] = {};
        #pragma unroll 8
        for (int d = 0; d < FT; d++) {
            float qv[4], kv[4];
            #pragma unroll
            for (int i = 0; i < 4; i++) qv[i] = Qs[(ty * 4 + i) * FLD + d];
            #pragma unroll
            for (int j = 0; j < 4; j++) kv[j] = Ks[(tx * 4 + j) * FLD + d];
            #pragma unroll
            for (int i = 0; i < 4; i++)
                #pragma unroll
                for (int j = 0; j < 4; j++)
                    s[i][j] += qv[i] * kv[j];
        }
        #pragma unroll
        for (int i = 0; i < 4; i++)
            #pragma unroll
            for (int j = 0; j < 4; j++)
                s[i][j] *= 0.125f;

        if (kt == qt) {
            #pragma unroll
            for (int i = 0; i < 4; i++)
                #pragma unroll
                for (int j = 0; j < 4; j++)
                    if (tx * 4 + j > ty * 4 + i) s[i][j] = -1e30f;
        }

        #pragma unroll
        for (int i = 0; i < 4; i++) {
            float tm = fmaxf(fmaxf(s[i][0], s[i][1]), fmaxf(s[i][2], s[i][3]));
            #pragma unroll
            for (int off = 8; off >= 1; off >>= 1)
                tm = fmaxf(tm, __shfl_xor_sync(0xffffffffu, tm, off));
            float mn = fmaxf(mrow[i], tm);
            float corr = __expf(mrow[i] - mn);
            float rs = 0.f;
            #pragma unroll
            for (int j = 0; j < 4; j++) {
                s[i][j] = __expf(s[i][j] - mn);
                rs += s[i][j];
            }
            #pragma unroll
            for (int off = 8; off >= 1; off >>= 1)
                rs += __shfl_xor_sync(0xffffffffu, rs, off);
            lrow[i] = lrow[i] * corr + rs;
            mrow[i] = mn;
            #pragma unroll
            for (int j = 0; j < 4; j++) o[i][j] *= corr;
        }

        #pragma unroll
        for (int i = 0; i < 4; i++)
            #pragma unroll
            for (int j = 0; j < 4; j++)
                Ps[(ty * 4 + i) * FLD + tx * 4 + j] = s[i][j];
        __syncthreads();

        #pragma unroll 8
        for (int c = 0; c < FT; c++) {
            float pv[4], vv[4];
            #pragma unroll
            for (int i = 0; i < 4; i++) pv[i] = Ps[(ty * 4 + i) * FLD + c];
            #pragma unroll
            for (int j = 0; j < 4; j++) vv[j] = Vs[c * FLD + tx * 4 + j];
            #pragma unroll
            for (int i = 0; i < 4; i++)
                #pragma unroll
                for (int j = 0; j < 4; j++)
                    o[i][j] += pv[i] * vv[j];
        }
    }

    #pragma unroll
    for (int i = 0; i < 4; i++) {
        float inv = 1.0f / lrow[i];
        int r = q0 + ty * 4 + i;
        float* op = g_attn + (size_t)(b * Sc + r) * Ec + h * HDc + tx * 4;
        #pragma unroll
        for (int j = 0; j < 4; j++) op[j] = o[i][j] * inv;
    }
    (void)attn_out;
}

// ===========================================================================
extern "C" void kernel_launch(void* const* d_in, const int* in_sizes, int n_in,
                              void* d_out, int out_size)
{
    const float* x      = (const float*)d_in[0];
    const float* qkv_w  = (const float*)d_in[1];
    const float* qkv_b  = (const float*)d_in[2];
    const float* out_w  = (const float*)d_in[3];
    const float* out_b  = (const float*)d_in[4];
    float* out = (float*)d_out;

    float* qkvp;
    float* attnp;
    cudaGetSymbolAddress((void**)&qkvp, g_qkv);
    cudaGetSymbolAddress((void**)&attnp, g_attn);

    constexpr int FLASH_SMEM = 4 * FT * FLD * (int)sizeof(float);  // 66560 B
    cudaFuncSetAttribute(flash_kernel,
                         cudaFuncAttributeMaxDynamicSharedMemorySize, FLASH_SMEM);

    // 1) QKV projection: [4096,1024] @ [3072,1024]^T + b -> g_qkv [4096,3072]
    dim3 g1(E3 / 128, Mc / 128);   // (24, 32)
    gemm_mma_kernel<<<g1, 256>>>(x, qkv_w, qkv_b, qkvp, Mc, E3, Ec);

    // 2) Causal flash attention -> g_attn [4096,1024]
    dim3 g2(Sc / FT, Hc, Bc);      // (32, 16, 2)
    flash_kernel<<<g2, 256, FLASH_SMEM>>>(qkvp, attnp);

    // 3) Output projection: [4096,1024] @ [1024,1024]^T + b -> d_out
    dim3 g3(Ec / 128, Mc / 128);   // (8, 32)
    gemm_mma_kernel<<<g3, 256>>>(attnp, out_w, out_b, out, Mc, Ec, Ec);
}

// round 4
// speedup vs baseline: 2.6575x; 1.6532x over previous
#include <cuda_runtime.h>
#include <cuda_bf16.h>
#include <cstdint>
#include <math.h>

// ===========================================================================
// Problem constants
// ===========================================================================
constexpr int Bc = 2;
constexpr int Sc = 2048;
constexpr int Ec = 1024;
constexpr int Hc = 16;
constexpr int HDc = 64;
constexpr int Mc = Bc * Sc;        // 4096
constexpr int E3 = 3 * Ec;         // 3072

// Scratch (no cudaMalloc allowed)
__device__ float g_qkv[Mc * E3];       // [M, 3E]
__device__ float g_attn[Mc * Ec];      // [M, E]

// ===========================================================================
// Shared helpers
// ===========================================================================
__device__ __forceinline__ uint32_t pack_bf16x2(__nv_bfloat16 lo, __nv_bfloat16 hi) {
    __nv_bfloat162 t = __halves2bfloat162(lo, hi);   // .x = lo (low 16 bits)
    return *reinterpret_cast<uint32_t*>(&t);
}

__device__ __forceinline__ uint32_t smem_u32(const void* p) {
    return (uint32_t)__cvta_generic_to_shared(p);
}

__device__ __forceinline__ void ldm_x4(uint32_t addr, uint32_t r[4]) {
    asm volatile("ldmatrix.sync.aligned.m8n8.x4.shared.b16 {%0,%1,%2,%3}, [%4];"
        : "=r"(r[0]), "=r"(r[1]), "=r"(r[2]), "=r"(r[3]) : "r"(addr));
}

__device__ __forceinline__ void mma_bf16(float c[4], const uint32_t a[4],
                                         uint32_t b0, uint32_t b1) {
    asm volatile(
        "mma.sync.aligned.m16n8k16.row.col.f32.bf16.bf16.f32 "
        "{%0,%1,%2,%3}, {%4,%5,%6,%7}, {%8,%9}, {%0,%1,%2,%3};"
        : "+f"(c[0]), "+f"(c[1]), "+f"(c[2]), "+f"(c[3])
        : "r"(a[0]), "r"(a[1]), "r"(a[2]), "r"(a[3]), "r"(b0), "r"(b1));
}

// Convert 8 fp32 -> 8 bf16 hi + 8 bf16 lo, store as uint4 into padded tiles.
template<int LD>
__device__ __forceinline__ void cvt_store(
    __nv_bfloat16* __restrict__ hit, __nv_bfloat16* __restrict__ lot,
    int row, int seg, const float* __restrict__ g)
{
    float4 a0 = *reinterpret_cast<const float4*>(g);
    float4 a1 = *reinterpret_cast<const float4*>(g + 4);
    float v[8] = {a0.x, a0.y, a0.z, a0.w, a1.x, a1.y, a1.z, a1.w};
    uint32_t hv[4], lv[4];
    #pragma unroll
    for (int j = 0; j < 4; j++) {
        __nv_bfloat16 h0 = __float2bfloat16(v[2*j]);
        __nv_bfloat16 h1 = __float2bfloat16(v[2*j+1]);
        float r0 = v[2*j]   - __bfloat162float(h0);
        float r1 = v[2*j+1] - __bfloat162float(h1);
        hv[j] = pack_bf16x2(h0, h1);
        lv[j] = pack_bf16x2(__float2bfloat16(r0), __float2bfloat16(r1));
    }
    *reinterpret_cast<uint4*>(hit + row * LD + seg) = make_uint4(hv[0], hv[1], hv[2], hv[3]);
    *reinterpret_cast<uint4*>(lot + row * LD + seg) = make_uint4(lv[0], lv[1], lv[2], lv[3]);
}

// ===========================================================================
// mma.sync bf16 GEMM (unchanged from round 3)
// CTA tile 128x128, 8 warps (2M x 4N), warp tile 64x32, K-chunk 32.
// ===========================================================================
constexpr int CHK = 32;
constexpr int LDT = 40;

__global__ __launch_bounds__(256, 2)
void gemm_mma_kernel(const float* __restrict__ A, const float* __restrict__ W,
                     const float* __restrict__ bias, float* __restrict__ C,
                     int M, int N, int K)
{
    __shared__ __align__(16) __nv_bfloat16 Ah[128 * LDT];
    __shared__ __align__(16) __nv_bfloat16 Al[128 * LDT];
    __shared__ __align__(16) __nv_bfloat16 Bh[128 * LDT];
    __shared__ __align__(16) __nv_bfloat16 Bl[128 * LDT];

    int tid  = threadIdx.x;
    int lane = tid & 31;
    int wid  = tid >> 5;
    int wm   = wid >> 2;
    int wn   = wid & 3;
    int bm   = blockIdx.y * 128;
    int bn   = blockIdx.x * 128;

    float acc[4][4][4] = {};

    int lrow  = lane & 15;
    int lhalf = (lane >> 4) * 8;

    for (int k0 = 0; k0 < K; k0 += CHK) {
        __syncthreads();
        #pragma unroll
        for (int i = 0; i < 2; i++) {
            int s   = tid + 256 * i;
            int row = s >> 2;
            int seg = (s & 3) * 8;
            cvt_store<LDT>(Ah, Al, row, seg, A + (size_t)(bm + row) * K + k0 + seg);
            cvt_store<LDT>(Bh, Bl, row, seg, W + (size_t)(bn + row) * K + k0 + seg);
        }
        __syncthreads();

        #pragma unroll
        for (int ks = 0; ks < 2; ks++) {
            int kk = ks * 16 + lhalf;

            uint32_t af[4][4];
            uint32_t bhf[2][4];
            #pragma unroll
            for (int mt = 0; mt < 4; mt++)
                ldm_x4(smem_u32(Ah + (wm * 64 + mt * 16 + lrow) * LDT + kk), af[mt]);
            #pragma unroll
            for (int nt = 0; nt < 2; nt++)
                ldm_x4(smem_u32(Bh + (wn * 32 + nt * 16 + lrow) * LDT + kk), bhf[nt]);

            #pragma unroll
            for (int mt = 0; mt < 4; mt++)
                #pragma unroll
                for (int nt = 0; nt < 2; nt++) {
                    mma_bf16(acc[mt][nt*2+0], af[mt], bhf[nt][0], bhf[nt][2]);
                    mma_bf16(acc[mt][nt*2+1], af[mt], bhf[nt][1], bhf[nt][3]);
                }

            uint32_t blf[2][4];
            #pragma unroll
            for (int nt = 0; nt < 2; nt++)
                ldm_x4(smem_u32(Bl + (wn * 32 + nt * 16 + lrow) * LDT + kk), blf[nt]);
            #pragma unroll
            for (int mt = 0; mt < 4; mt++)
                #pragma unroll
                for (int nt = 0; nt < 2; nt++) {
                    mma_bf16(acc[mt][nt*2+0], af[mt], blf[nt][0], blf[nt][2]);
                    mma_bf16(acc[mt][nt*2+1], af[mt], blf[nt][1], blf[nt][3]);
                }

            uint32_t alf[4][4];
            #pragma unroll
            for (int mt = 0; mt < 4; mt++)
                ldm_x4(smem_u32(Al + (wm * 64 + mt * 16 + lrow) * LDT + kk), alf[mt]);
            #pragma unroll
            for (int mt = 0; mt < 4; mt++)
                #pragma unroll
                for (int nt = 0; nt < 2; nt++) {
                    mma_bf16(acc[mt][nt*2+0], alf[mt], bhf[nt][0], bhf[nt][2]);
                    mma_bf16(acc[mt][nt*2+1], alf[mt], bhf[nt][1], bhf[nt][3]);
                }
        }
    }

    #pragma unroll
    for (int mt = 0; mt < 4; mt++) {
        int r0 = bm + wm * 64 + mt * 16 + (lane >> 2);
        #pragma unroll
        for (int n8 = 0; n8 < 4; n8++) {
            int col = bn + wn * 32 + n8 * 8 + (lane & 3) * 2;
            float b0 = bias[col], b1 = bias[col + 1];
            float2 v0 = make_float2(acc[mt][n8][0] + b0, acc[mt][n8][1] + b1);
            float2 v1 = make_float2(acc[mt][n8][2] + b0, acc[mt][n8][3] + b1);
            *reinterpret_cast<float2*>(C + (size_t)r0 * N + col) = v0;
            *reinterpret_cast<float2*>(C + (size_t)(r0 + 8) * N + col) = v1;
        }
    }
}

// ===========================================================================
// Flash attention (causal) on tensor cores, split-bf16 both GEMMs.
// CTA: 128 q-rows x one (b,h). 8 warps x 16 q-rows. 64-key tiles.
// ===========================================================================
constexpr int LDH = 72;    // padded bf16 leading dim (144B rows: conflict-free)

// smem element offsets
constexpr int FQH = 0;
constexpr int FQL = 128 * LDH;           // 9216
constexpr int FKH = 2 * 128 * LDH;       // 18432
constexpr int FKL = FKH + 64 * LDH;      // 23040
constexpr int FVH = FKL + 64 * LDH;      // 27648
constexpr int FVL = FVH + 64 * LDH;      // 32256
constexpr int FLASH_ELEMS = FVL + 64 * LDH;   // 36864
constexpr int FLASH_SMEM = FLASH_ELEMS * 2;   // 73728 B

__global__ __launch_bounds__(256, 2)
void flash_tc_kernel(const float* __restrict__ qkv)
{
    extern __shared__ __nv_bfloat16 fs[];
    __nv_bfloat16* Qh  = fs + FQH;
    __nv_bfloat16* Ql  = fs + FQL;
    __nv_bfloat16* Kh  = fs + FKH;
    __nv_bfloat16* Kl  = fs + FKL;
    __nv_bfloat16* Vth = fs + FVH;
    __nv_bfloat16* Vtl = fs + FVL;

    int tid  = threadIdx.x;
    int lane = tid & 31;
    int wq   = tid >> 5;                        // warp: q rows wq*16..+15
    int qt   = gridDim.x - 1 - blockIdx.x;      // heavy q-tiles first
    int h    = blockIdx.y;
    int b    = blockIdx.z;
    int q0   = qt * 128;

    // ---- load + split Q (128 x 64) once ----
    {
        int row  = tid >> 1;
        int dseg = (tid & 1) * 32;
        const float* qp = qkv + (size_t)(b * Sc + q0 + row) * E3 + h * HDc + dseg;
        cvt_store<LDH>(Qh, Ql, row, dseg,      qp);
        cvt_store<LDH>(Qh, Ql, row, dseg + 8,  qp + 8);
        cvt_store<LDH>(Qh, Ql, row, dseg + 16, qp + 16);
        cvt_store<LDH>(Qh, Ql, row, dseg + 24, qp + 24);
    }

    float o[8][4] = {};                    // O accum: 16 q-rows x 64 d
    float mrow[2] = {-1e30f, -1e30f};
    float lsum[2] = {0.f, 0.f};

    int lrow = lane & 15;
    int lh8  = (lane >> 4) * 8;
    int warp_row_lo = q0 + wq * 16;        // warp's first q row

    int nkt = 2 * qt + 2;
    for (int kt = 0; kt < nkt; kt++) {
        int kc0 = kt * 64;
        __syncthreads();   // previous tile's readers done

        // ---- load + split K (64 keys x 64 d), V transposed (64 d x 64 keys) ----
        {
            int key  = tid >> 2;
            int dseg = (tid & 3) * 16;
            const float* kp = qkv + (size_t)(b * Sc + kc0 + key) * E3 + Ec + h * HDc + dseg;
            cvt_store<LDH>(Kh, Kl, key, dseg,     kp);
            cvt_store<LDH>(Kh, Kl, key, dseg + 8, kp + 8);

            int kp2 = tid & 31;            // key pair: keys 2*kp2, 2*kp2+1
            int ds2 = (tid >> 5) * 8;      // 8 d values
            const float* vp0 = qkv + (size_t)(b * Sc + kc0 + 2 * kp2) * E3 + 2 * Ec + h * HDc + ds2;
            const float* vp1 = vp0 + E3;
            float4 x0 = *reinterpret_cast<const float4*>(vp0);
            float4 x1 = *reinterpret_cast<const float4*>(vp0 + 4);
            float4 y0 = *reinterpret_cast<const float4*>(vp1);
            float4 y1 = *reinterpret_cast<const float4*>(vp1 + 4);
            float v0[8] = {x0.x, x0.y, x0.z, x0.w, x1.x, x1.y, x1.z, x1.w};
            float v1[8] = {y0.x, y0.y, y0.z, y0.w, y1.x, y1.y, y1.z, y1.w};
            #pragma unroll
            for (int d = 0; d < 8; d++) {
                __nv_bfloat16 h0 = __float2bfloat16(v0[d]);
                __nv_bfloat16 h1 = __float2bfloat16(v1[d]);
                float r0 = v0[d] - __bfloat162float(h0);
                float r1 = v1[d] - __bfloat162float(h1);
                int eo = (ds2 + d) * LDH + 2 * kp2;
                *reinterpret_cast<uint32_t*>(Vth + eo) = pack_bf16x2(h0, h1);
                *reinterpret_cast<uint32_t*>(Vtl + eo) =
                    pack_bf16x2(__float2bfloat16(r0), __float2bfloat16(r1));
            }
        }
        __syncthreads();

        // warps entirely above the diagonal for this key tile: nothing to do
        if (kc0 > warp_row_lo + 15) continue;
        bool domask = (kc0 + 63 > warp_row_lo);

        // ---- S = Q K^T (split 3-pass) ----
        float s[8][4] = {};
        #pragma unroll
        for (int ksj = 0; ksj < 4; ksj++) {
            int kk = ksj * 16 + lh8;
            uint32_t aq[4], al[4];
            ldm_x4(smem_u32(Qh + (wq * 16 + lrow) * LDH + kk), aq);
            ldm_x4(smem_u32(Ql + (wq * 16 + lrow) * LDH + kk), al);
            #pragma unroll
            for (int nt = 0; nt < 4; nt++) {
                uint32_t kh[4], kl[4];
                ldm_x4(smem_u32(Kh + (nt * 16 + lrow) * LDH + kk), kh);
                ldm_x4(smem_u32(Kl + (nt * 16 + lrow) * LDH + kk), kl);
                mma_bf16(s[2*nt+0], aq, kh[0], kh[2]);
                mma_bf16(s[2*nt+1], aq, kh[1], kh[3]);
                mma_bf16(s[2*nt+0], aq, kl[0], kl[2]);
                mma_bf16(s[2*nt+1], aq, kl[1], kl[3]);
                mma_bf16(s[2*nt+0], al, kh[0], kh[2]);
                mma_bf16(s[2*nt+1], al, kh[1], kh[3]);
            }
        }

        // ---- scale + causal mask ----
        int r_lo = warp_row_lo + (lane >> 2);
        #pragma unroll
        for (int n8 = 0; n8 < 8; n8++) {
            int c0 = kc0 + n8 * 8 + (lane & 3) * 2;
            #pragma unroll
            for (int cc = 0; cc < 4; cc++) {
                float v = s[n8][cc] * 0.125f;
                if (domask) {
                    int col = c0 + (cc & 1);
                    int row = r_lo + (cc >> 1) * 8;
                    if (col > row) v = -1e30f;
                }
                s[n8][cc] = v;
            }
        }

        // ---- online softmax (rows split across 4 lanes) ----
        #pragma unroll
        for (int hh = 0; hh < 2; hh++) {
            float tm = -1e30f;
            #pragma unroll
            for (int n8 = 0; n8 < 8; n8++)
                tm = fmaxf(tm, fmaxf(s[n8][2*hh], s[n8][2*hh+1]));
            tm = fmaxf(tm, __shfl_xor_sync(0xffffffffu, tm, 1));
            tm = fmaxf(tm, __shfl_xor_sync(0xffffffffu, tm, 2));
            float mn = fmaxf(mrow[hh], tm);
            float corr = __expf(mrow[hh] - mn);
            mrow[hh] = mn;
            float rs = 0.f;
            #pragma unroll
            for (int n8 = 0; n8 < 8; n8++) {
                s[n8][2*hh]   = __expf(s[n8][2*hh]   - mn);
                s[n8][2*hh+1] = __expf(s[n8][2*hh+1] - mn);
                rs += s[n8][2*hh] + s[n8][2*hh+1];
            }
            rs += __shfl_xor_sync(0xffffffffu, rs, 1);
            rs += __shfl_xor_sync(0xffffffffu, rs, 2);
            lsum[hh] = lsum[hh] * corr + rs;
            #pragma unroll
            for (int n8 = 0; n8 < 8; n8++) {
                o[n8][2*hh]   *= corr;
                o[n8][2*hh+1] *= corr;
            }
        }

        // ---- O += P V (split 3-pass, P frags straight from registers) ----
        #pragma unroll
        for (int j = 0; j < 4; j++) {
            uint32_t ph[4], pl[4];
            #pragma unroll
            for (int q2 = 0; q2 < 2; q2++) {       // q2=0: s[2j], q2=1: s[2j+1]
                const float* sp = s[2*j + q2];
                #pragma unroll
                for (int hh = 0; hh < 2; hh++) {
                    __nv_bfloat16 h0 = __float2bfloat16(sp[2*hh]);
                    __nv_bfloat16 h1 = __float2bfloat16(sp[2*hh+1]);
                    float r0 = sp[2*hh]   - __bfloat162float(h0);
                    float r1 = sp[2*hh+1] - __bfloat162float(h1);
                    ph[q2*2 + hh] = pack_bf16x2(h0, h1);
                    pl[q2*2 + hh] = pack_bf16x2(__float2bfloat16(r0), __float2bfloat16(r1));
                }
            }
            // a0=(r,k) a1=(r+8,k) a2=(r,k+8) a3=(r+8,k+8):
            uint32_t pA[4] = {ph[0], ph[1], ph[2], ph[3]};
            uint32_t pL[4] = {pl[0], pl[1], pl[2], pl[3]};
            #pragma unroll
            for (int nt = 0; nt < 4; nt++) {
                uint32_t vh[4], vl[4];
                ldm_x4(smem_u32(Vth + (nt * 16 + lrow) * LDH + j * 16 + lh8), vh);
                ldm_x4(smem_u32(Vtl + (nt * 16 + lrow) * LDH + j * 16 + lh8), vl);
                mma_bf16(o[2*nt+0], pA, vh[0], vh[2]);
                mma_bf16(o[2*nt+1], pA, vh[1], vh[3]);
                mma_bf16(o[2*nt+0], pA, vl[0], vl[2]);
                mma_bf16(o[2*nt+1], pA, vl[1], vl[3]);
                mma_bf16(o[2*nt+0], pL, vh[0], vh[2]);
                mma_bf16(o[2*nt+1], pL, vh[1], vh[3]);
            }
        }
    }

    // ---- epilogue: normalize, write g_attn[b][s][h*64 + d] ----
    #pragma unroll
    for (int hh = 0; hh < 2; hh++) {
        float inv = 1.0f / lsum[hh];
        int row = warp_row_lo + (lane >> 2) + hh * 8;
        float* op = g_attn + (size_t)(b * Sc + row) * Ec + h * HDc;
        #pragma unroll
        for (int n8 = 0; n8 < 8; n8++) {
            int d = n8 * 8 + (lane & 3) * 2;
            float2 v = make_float2(o[n8][2*hh] * inv, o[n8][2*hh+1] * inv);
            *reinterpret_cast<float2*>(op + d) = v;
        }
    }
}

// ===========================================================================
extern "C" void kernel_launch(void* const* d_in, const int* in_sizes, int n_in,
                              void* d_out, int out_size)
{
    const float* x      = (const float*)d_in[0];
    const float* qkv_w  = (const float*)d_in[1];
    const float* qkv_b  = (const float*)d_in[2];
    const float* out_w  = (const float*)d_in[3];
    const float* out_b  = (const float*)d_in[4];
    float* out = (float*)d_out;

    float* qkvp;
    float* attnp;
    cudaGetSymbolAddress((void**)&qkvp, g_qkv);
    cudaGetSymbolAddress((void**)&attnp, g_attn);

    cudaFuncSetAttribute(flash_tc_kernel,
                         cudaFuncAttributeMaxDynamicSharedMemorySize, FLASH_SMEM);

    // 1) QKV projection: [4096,1024] @ [3072,1024]^T + b -> g_qkv
    dim3 g1(E3 / 128, Mc / 128);   // (24, 32)
    gemm_mma_kernel<<<g1, 256>>>(x, qkv_w, qkv_b, qkvp, Mc, E3, Ec);

    // 2) Causal flash attention (tensor cores) -> g_attn
    dim3 g2(Sc / 128, Hc, Bc);     // (16, 16, 2)
    flash_tc_kernel<<<g2, 256, FLASH_SMEM>>>(qkvp);

    // 3) Output projection: [4096,1024] @ [1024,1024]^T + b -> d_out
    dim3 g3(Ec / 128, Mc / 128);   // (8, 32)
    gemm_mma_kernel<<<g3, 256>>>(attnp, out_w, out_b, out, Mc, Ec, Ec);
}

// round 5
// speedup vs baseline: 2.7481x; 1.0341x over previous
#include <cuda_runtime.h>
#include <cuda_bf16.h>
#include <cstdint>
#include <math.h>

// ===========================================================================
// Problem constants
// ===========================================================================
constexpr int Bc = 2;
constexpr int Sc = 2048;
constexpr int Ec = 1024;
constexpr int Hc = 16;
constexpr int HDc = 64;
constexpr int Mc = Bc * Sc;        // 4096
constexpr int E3 = 3 * Ec;         // 3072

// Scratch (no cudaMalloc allowed) — split bf16 hi/lo pairs
__device__ __nv_bfloat16 g_xh[Mc * Ec],  g_xl[Mc * Ec];
__device__ __nv_bfloat16 g_wqh[E3 * Ec], g_wql[E3 * Ec];
__device__ __nv_bfloat16 g_woh[Ec * Ec], g_wol[Ec * Ec];
__device__ __nv_bfloat16 g_qkvh[Mc * E3], g_qkvl[Mc * E3];
__device__ __nv_bfloat16 g_ah[Mc * Ec],  g_al[Mc * Ec];

// ===========================================================================
// Helpers
// ===========================================================================
__device__ __forceinline__ uint32_t pack_bf16x2(__nv_bfloat16 lo, __nv_bfloat16 hi) {
    __nv_bfloat162 t = __halves2bfloat162(lo, hi);   // .x = lo (low 16 bits)
    return *reinterpret_cast<uint32_t*>(&t);
}
__device__ __forceinline__ uint32_t smem_u32(const void* p) {
    return (uint32_t)__cvta_generic_to_shared(p);
}
__device__ __forceinline__ void ldm_x4(uint32_t addr, uint32_t r[4]) {
    asm volatile("ldmatrix.sync.aligned.m8n8.x4.shared.b16 {%0,%1,%2,%3}, [%4];"
        : "=r"(r[0]), "=r"(r[1]), "=r"(r[2]), "=r"(r[3]) : "r"(addr));
}
__device__ __forceinline__ void ldm_x4_t(uint32_t addr, uint32_t r[4]) {
    asm volatile("ldmatrix.sync.aligned.m8n8.x4.trans.shared.b16 {%0,%1,%2,%3}, [%4];"
        : "=r"(r[0]), "=r"(r[1]), "=r"(r[2]), "=r"(r[3]) : "r"(addr));
}
__device__ __forceinline__ void mma_bf16(float c[4], const uint32_t a[4],
                                         uint32_t b0, uint32_t b1) {
    asm volatile(
        "mma.sync.aligned.m16n8k16.row.col.f32.bf16.bf16.f32 "
        "{%0,%1,%2,%3}, {%4,%5,%6,%7}, {%8,%9}, {%0,%1,%2,%3};"
        : "+f"(c[0]), "+f"(c[1]), "+f"(c[2]), "+f"(c[3])
        : "r"(a[0]), "r"(a[1]), "r"(a[2]), "r"(a[3]), "r"(b0), "r"(b1));
}
#define CP16(dst, src) \
    asm volatile("cp.async.cg.shared.global [%0], [%1], 16;" :: "r"(dst), "l"(src))
#define CP_COMMIT() asm volatile("cp.async.commit_group;")
#define CP_WAIT0()  asm volatile("cp.async.wait_group 0;")
#define CP_WAIT1()  asm volatile("cp.async.wait_group 1;")

__device__ __forceinline__ void split2(float v, __nv_bfloat16& h, __nv_bfloat16& l) {
    h = __float2bfloat16(v);
    l = __float2bfloat16(v - __bfloat162float(h));
}

// ===========================================================================
// Prepass: split fp32 array into bf16 hi/lo arrays (vectorized by 4)
// ===========================================================================
__global__ void split_fp32_kernel(const float* __restrict__ src,
                                  __nv_bfloat16* __restrict__ hi,
                                  __nv_bfloat16* __restrict__ lo, int n4)
{
    int i = blockIdx.x * blockDim.x + threadIdx.x;
    if (i >= n4) return;
    float4 v = reinterpret_cast<const float4*>(src)[i];
    __nv_bfloat16 h0, h1, h2, h3, l0, l1, l2, l3;
    split2(v.x, h0, l0); split2(v.y, h1, l1);
    split2(v.z, h2, l2); split2(v.w, h3, l3);
    reinterpret_cast<uint2*>(hi)[i] = make_uint2(pack_bf16x2(h0, h1), pack_bf16x2(h2, h3));
    reinterpret_cast<uint2*>(lo)[i] = make_uint2(pack_bf16x2(l0, l1), pack_bf16x2(l2, l3));
}

// ===========================================================================
// bf16 GEMM, cp.async double-buffered:
//   C[M,N] = (Ah+Al)[M,K] @ (Bh+Bl)[N,K]^T + bias   (3-pass split)
// CTA 128x128, 8 warps (2Mx4N), warp tile 64x32, K-chunk 32, 2 stages.
// SPLIT_OUT: write Ch/Cl bf16 hi/lo instead of fp32 C.
// ===========================================================================
constexpr int LDT = 40;                     // padded bf16 leading dim (80B rows)
constexpr int STG = 128 * LDT;              // 5120 elems per tile
constexpr int STAGE = 4 * STG;              // 20480 elems per stage
constexpr int GEMM_SMEM = 2 * STAGE * 2;    // 81920 B

template<bool SPLIT_OUT>
__global__ __launch_bounds__(256, 2)
void gemm_bf16_kernel(const __nv_bfloat16* __restrict__ Ahg, const __nv_bfloat16* __restrict__ Alg,
                      const __nv_bfloat16* __restrict__ Bhg, const __nv_bfloat16* __restrict__ Blg,
                      const float* __restrict__ bias,
                      float* __restrict__ C,
                      __nv_bfloat16* __restrict__ Ch, __nv_bfloat16* __restrict__ Cl,
                      int M, int N, int K)
{
    extern __shared__ __nv_bfloat16 sm[];
    int tid  = threadIdx.x;
    int lane = tid & 31;
    int wid  = tid >> 5;
    int wm   = wid >> 2;
    int wn   = wid & 3;
    int bm   = blockIdx.y * 128;
    int bn   = blockIdx.x * 128;

    int lrow  = lane & 15;
    int lhalf = (lane >> 4) * 8;

    int r0  = tid >> 2;            // 0..63
    int seg = (tid & 3) * 8;       // elem offset 0,8,16,24

    const __nv_bfloat16* gs0 = Ahg + (size_t)bm * K;
    const __nv_bfloat16* gs1 = Alg + (size_t)bm * K;
    const __nv_bfloat16* gs2 = Bhg + (size_t)bn * K;
    const __nv_bfloat16* gs3 = Blg + (size_t)bn * K;

    auto load_stage = [&](int stg, int k0) {
        __nv_bfloat16* st = sm + stg * STAGE;
        const __nv_bfloat16* gp[4] = {gs0, gs1, gs2, gs3};
        #pragma unroll
        for (int a = 0; a < 4; a++) {
            #pragma unroll
            for (int i = 0; i < 2; i++) {
                int row = r0 + 64 * i;
                CP16(smem_u32(st + a * STG + row * LDT + seg),
                     gp[a] + (size_t)row * K + k0 + seg);
            }
        }
    };

    float acc[4][4][4] = {};

    load_stage(0, 0);
    CP_COMMIT();

    const int nch = K / 32;
    for (int c = 0; c < nch; c++) {
        if (c + 1 < nch) {
            load_stage((c + 1) & 1, (c + 1) * 32);
            CP_COMMIT();
            CP_WAIT1();
        } else {
            CP_WAIT0();
        }
        __syncthreads();

        __nv_bfloat16* st = sm + (c & 1) * STAGE;
        __nv_bfloat16* Ah = st;
        __nv_bfloat16* Al = st + STG;
        __nv_bfloat16* Bh = st + 2 * STG;
        __nv_bfloat16* Bl = st + 3 * STG;

        #pragma unroll
        for (int ks = 0; ks < 2; ks++) {
            int kk = ks * 16 + lhalf;

            uint32_t af[4][4];
            uint32_t bhf[2][4];
            #pragma unroll
            for (int mt = 0; mt < 4; mt++)
                ldm_x4(smem_u32(Ah + (wm * 64 + mt * 16 + lrow) * LDT + kk), af[mt]);
            #pragma unroll
            for (int nt = 0; nt < 2; nt++)
                ldm_x4(smem_u32(Bh + (wn * 32 + nt * 16 + lrow) * LDT + kk), bhf[nt]);

            #pragma unroll
            for (int mt = 0; mt < 4; mt++)
                #pragma unroll
                for (int nt = 0; nt < 2; nt++) {
                    mma_bf16(acc[mt][nt*2+0], af[mt], bhf[nt][0], bhf[nt][2]);
                    mma_bf16(acc[mt][nt*2+1], af[mt], bhf[nt][1], bhf[nt][3]);
                }

            uint32_t blf[2][4];
            #pragma unroll
            for (int nt = 0; nt < 2; nt++)
                ldm_x4(smem_u32(Bl + (wn * 32 + nt * 16 + lrow) * LDT + kk), blf[nt]);
            #pragma unroll
            for (int mt = 0; mt < 4; mt++)
                #pragma unroll
                for (int nt = 0; nt < 2; nt++) {
                    mma_bf16(acc[mt][nt*2+0], af[mt], blf[nt][0], blf[nt][2]);
                    mma_bf16(acc[mt][nt*2+1], af[mt], blf[nt][1], blf[nt][3]);
                }

            uint32_t alf[4][4];
            #pragma unroll
            for (int mt = 0; mt < 4; mt++)
                ldm_x4(smem_u32(Al + (wm * 64 + mt * 16 + lrow) * LDT + kk), alf[mt]);
            #pragma unroll
            for (int mt = 0; mt < 4; mt++)
                #pragma unroll
                for (int nt = 0; nt < 2; nt++) {
                    mma_bf16(acc[mt][nt*2+0], alf[mt], bhf[nt][0], bhf[nt][2]);
                    mma_bf16(acc[mt][nt*2+1], alf[mt], bhf[nt][1], bhf[nt][3]);
                }
        }
        __syncthreads();
    }

    // ---- epilogue ----
    #pragma unroll
    for (int mt = 0; mt < 4; mt++) {
        int row = bm + wm * 64 + mt * 16 + (lane >> 2);
        #pragma unroll
        for (int n8 = 0; n8 < 4; n8++) {
            int col = bn + wn * 32 + n8 * 8 + (lane & 3) * 2;
            float b0 = bias[col], b1 = bias[col + 1];
            float v0 = acc[mt][n8][0] + b0, v1 = acc[mt][n8][1] + b1;
            float v2 = acc[mt][n8][2] + b0, v3 = acc[mt][n8][3] + b1;
            if (SPLIT_OUT) {
                __nv_bfloat16 h0, h1, h2, h3, l0, l1, l2, l3;
                split2(v0, h0, l0); split2(v1, h1, l1);
                split2(v2, h2, l2); split2(v3, h3, l3);
                *reinterpret_cast<uint32_t*>(Ch + (size_t)row * N + col)       = pack_bf16x2(h0, h1);
                *reinterpret_cast<uint32_t*>(Cl + (size_t)row * N + col)       = pack_bf16x2(l0, l1);
                *reinterpret_cast<uint32_t*>(Ch + (size_t)(row + 8) * N + col) = pack_bf16x2(h2, h3);
                *reinterpret_cast<uint32_t*>(Cl + (size_t)(row + 8) * N + col) = pack_bf16x2(l2, l3);
            } else {
                *reinterpret_cast<float2*>(C + (size_t)row * N + col)       = make_float2(v0, v1);
                *reinterpret_cast<float2*>(C + (size_t)(row + 8) * N + col) = make_float2(v2, v3);
            }
        }
    }
}

// ===========================================================================
// Flash attention (causal), tensor cores, bf16 hi/lo inputs, cp.async pipeline.
// CTA: 128 q-rows x one (b,h). 8 warps x 16 q-rows. 64-key tiles, 2 KV stages.
// ===========================================================================
constexpr int LDH = 72;                      // 144B rows, conflict-free
constexpr int FQ  = 128 * LDH;               // 9216 elems per Q tile
constexpr int FKV = 64 * LDH;                // 4608 elems per KV tile
constexpr int KVSTAGE = 4 * FKV;             // Kh,Kl,Vh,Vl = 18432 elems
constexpr int FLASH_ELEMS = 2 * FQ + 2 * KVSTAGE;   // 55296
constexpr int FLASH_SMEM  = FLASH_ELEMS * 2;        // 110592 B

__global__ __launch_bounds__(256, 2)
void flash_tc_kernel(const __nv_bfloat16* __restrict__ qh,
                     const __nv_bfloat16* __restrict__ ql)
{
    extern __shared__ __nv_bfloat16 fs[];
    __nv_bfloat16* Qh = fs;
    __nv_bfloat16* Ql = fs + FQ;
    __nv_bfloat16* KV = fs + 2 * FQ;          // 2 stages of {Kh,Kl,Vh,Vl}

    int tid  = threadIdx.x;
    int lane = tid & 31;
    int wq   = tid >> 5;
    int qt   = gridDim.x - 1 - blockIdx.x;    // heavy q-tiles first
    int h    = blockIdx.y;
    int b    = blockIdx.z;
    int q0   = qt * 128;

    int lrow = lane & 15;
    int lh8  = (lane >> 4) * 8;
    int warp_row_lo = q0 + wq * 16;

    // ---- Q tile loads (cp.async): 128 rows x 8 chunks x 2 arrays ----
    {
        #pragma unroll
        for (int i = 0; i < 4; i++) {
            int s   = tid + 256 * i;
            int row = s >> 3;
            int ch  = (s & 7) * 8;
            size_t go = (size_t)(b * Sc + q0 + row) * E3 + h * HDc + ch;
            CP16(smem_u32(Qh + row * LDH + ch), qh + go);
            CP16(smem_u32(Ql + row * LDH + ch), ql + go);
        }
    }

    auto load_kv = [&](int stg, int kc0) {
        __nv_bfloat16* st = KV + stg * KVSTAGE;
        #pragma unroll
        for (int i = 0; i < 2; i++) {
            int s   = tid + 256 * i;
            int row = s >> 3;
            int ch  = (s & 7) * 8;
            size_t gk = (size_t)(b * Sc + kc0 + row) * E3 + Ec + h * HDc + ch;
            size_t gv = gk + Ec;
            uint32_t so = row * LDH + ch;
            CP16(smem_u32(st + so),           qh + gk);   // Kh
            CP16(smem_u32(st + FKV + so),     ql + gk);   // Kl
            CP16(smem_u32(st + 2*FKV + so),   qh + gv);   // Vh
            CP16(smem_u32(st + 3*FKV + so),   ql + gv);   // Vl
        }
    };

    load_kv(0, 0);
    CP_COMMIT();   // group 0: Q + KV0

    float o[8][4] = {};
    float mrow[2] = {-1e30f, -1e30f};
    float lsum[2] = {0.f, 0.f};

    const int nkt = 2 * qt + 2;
    for (int kt = 0; kt < nkt; kt++) {
        int kc0 = kt * 64;
        if (kt + 1 < nkt) {
            load_kv((kt + 1) & 1, (kt + 1) * 64);
            CP_COMMIT();
            CP_WAIT1();
        } else {
            CP_WAIT0();
        }
        __syncthreads();

        __nv_bfloat16* st  = KV + (kt & 1) * KVSTAGE;
        __nv_bfloat16* Kh  = st;
        __nv_bfloat16* Kl  = st + FKV;
        __nv_bfloat16* Vh  = st + 2 * FKV;
        __nv_bfloat16* Vl  = st + 3 * FKV;

        if (kc0 <= warp_row_lo + 15) {
            bool domask = (kc0 + 63 > warp_row_lo);

            // ---- S = Q K^T (split 3-pass) ----
            float s[8][4] = {};
            #pragma unroll
            for (int ksj = 0; ksj < 4; ksj++) {
                int kk = ksj * 16 + lh8;
                uint32_t aq[4], al[4];
                ldm_x4(smem_u32(Qh + (wq * 16 + lrow) * LDH + kk), aq);
                ldm_x4(smem_u32(Ql + (wq * 16 + lrow) * LDH + kk), al);
                #pragma unroll
                for (int nt = 0; nt < 4; nt++) {
                    uint32_t kh[4], kl[4];
                    ldm_x4(smem_u32(Kh + (nt * 16 + lrow) * LDH + kk), kh);
                    ldm_x4(smem_u32(Kl + (nt * 16 + lrow) * LDH + kk), kl);
                    mma_bf16(s[2*nt+0], aq, kh[0], kh[2]);
                    mma_bf16(s[2*nt+1], aq, kh[1], kh[3]);
                    mma_bf16(s[2*nt+0], aq, kl[0], kl[2]);
                    mma_bf16(s[2*nt+1], aq, kl[1], kl[3]);
                    mma_bf16(s[2*nt+0], al, kh[0], kh[2]);
                    mma_bf16(s[2*nt+1], al, kh[1], kh[3]);
                }
            }

            // ---- scale + causal mask ----
            int r_lo = warp_row_lo + (lane >> 2);
            #pragma unroll
            for (int n8 = 0; n8 < 8; n8++) {
                int c0 = kc0 + n8 * 8 + (lane & 3) * 2;
                #pragma unroll
                for (int cc = 0; cc < 4; cc++) {
                    float v = s[n8][cc] * 0.125f;
                    if (domask) {
                        int col = c0 + (cc & 1);
                        int row = r_lo + (cc >> 1) * 8;
                        if (col > row) v = -1e30f;
                    }
                    s[n8][cc] = v;
                }
            }

            // ---- online softmax ----
            #pragma unroll
            for (int hh = 0; hh < 2; hh++) {
                float tm = -1e30f;
                #pragma unroll
                for (int n8 = 0; n8 < 8; n8++)
                    tm = fmaxf(tm, fmaxf(s[n8][2*hh], s[n8][2*hh+1]));
                tm = fmaxf(tm, __shfl_xor_sync(0xffffffffu, tm, 1));
                tm = fmaxf(tm, __shfl_xor_sync(0xffffffffu, tm, 2));
                float mn = fmaxf(mrow[hh], tm);
                float corr = __expf(mrow[hh] - mn);
                mrow[hh] = mn;
                float rs = 0.f;
                #pragma unroll
                for (int n8 = 0; n8 < 8; n8++) {
                    s[n8][2*hh]   = __expf(s[n8][2*hh]   - mn);
                    s[n8][2*hh+1] = __expf(s[n8][2*hh+1] - mn);
                    rs += s[n8][2*hh] + s[n8][2*hh+1];
                }
                rs += __shfl_xor_sync(0xffffffffu, rs, 1);
                rs += __shfl_xor_sync(0xffffffffu, rs, 2);
                lsum[hh] = lsum[hh] * corr + rs;
                #pragma unroll
                for (int n8 = 0; n8 < 8; n8++) {
                    o[n8][2*hh]   *= corr;
                    o[n8][2*hh+1] *= corr;
                }
            }

            // ---- O += P V (split 3-pass; V via trans ldmatrix) ----
            #pragma unroll
            for (int j = 0; j < 4; j++) {       // key chunk of 16
                uint32_t pA[4], pL[4];
                #pragma unroll
                for (int q2 = 0; q2 < 2; q2++) {
                    const float* sp = s[2*j + q2];
                    #pragma unroll
                    for (int hh = 0; hh < 2; hh++) {
                        __nv_bfloat16 h0, h1, l0, l1;
                        split2(sp[2*hh],   h0, l0);
                        split2(sp[2*hh+1], h1, l1);
                        pA[q2*2 + hh] = pack_bf16x2(h0, h1);
                        pL[q2*2 + hh] = pack_bf16x2(l0, l1);
                    }
                }
                #pragma unroll
                for (int nt = 0; nt < 4; nt++) {   // d chunk of 16
                    uint32_t vh[4], vl[4];
                    ldm_x4_t(smem_u32(Vh + (j * 16 + lrow) * LDH + nt * 16 + lh8), vh);
                    ldm_x4_t(smem_u32(Vl + (j * 16 + lrow) * LDH + nt * 16 + lh8), vl);
                    mma_bf16(o[2*nt+0], pA, vh[0], vh[1]);
                    mma_bf16(o[2*nt+1], pA, vh[2], vh[3]);
                    mma_bf16(o[2*nt+0], pA, vl[0], vl[1]);
                    mma_bf16(o[2*nt+1], pA, vl[2], vl[3]);
                    mma_bf16(o[2*nt+0], pL, vh[0], vh[1]);
                    mma_bf16(o[2*nt+1], pL, vh[2], vh[3]);
                }
            }
        }
        __syncthreads();   // buffer reuse safety for kt+2's load
    }

    // ---- epilogue: normalize, split, write g_ah/g_al ----
    #pragma unroll
    for (int hh = 0; hh < 2; hh++) {
        float inv = 1.0f / lsum[hh];
        int row = warp_row_lo + (lane >> 2) + hh * 8;
        size_t base = (size_t)(b * Sc + row) * Ec + h * HDc;
        #pragma unroll
        for (int n8 = 0; n8 < 8; n8++) {
            int d = n8 * 8 + (lane & 3) * 2;
            float v0 = o[n8][2*hh] * inv;
            float v1 = o[n8][2*hh+1] * inv;
            __nv_bfloat16 h0, h1, l0, l1;
            split2(v0, h0, l0); split2(v1, h1, l1);
            *reinterpret_cast<uint32_t*>(g_ah + base + d) = pack_bf16x2(h0, h1);
            *reinterpret_cast<uint32_t*>(g_al + base + d) = pack_bf16x2(l0, l1);
        }
    }
}

// ===========================================================================
extern "C" void kernel_launch(void* const* d_in, const int* in_sizes, int n_in,
                              void* d_out, int out_size)
{
    const float* x      = (const float*)d_in[0];
    const float* qkv_w  = (const float*)d_in[1];
    const float* qkv_b  = (const float*)d_in[2];
    const float* out_w  = (const float*)d_in[3];
    const float* out_b  = (const float*)d_in[4];
    float* out = (float*)d_out;

    __nv_bfloat16 *xh, *xl, *wqh, *wql, *woh, *wol, *qkvh, *qkvl, *ah, *al;
    cudaGetSymbolAddress((void**)&xh,  g_xh);   cudaGetSymbolAddress((void**)&xl,  g_xl);
    cudaGetSymbolAddress((void**)&wqh, g_wqh);  cudaGetSymbolAddress((void**)&wql, g_wql);
    cudaGetSymbolAddress((void**)&woh, g_woh);  cudaGetSymbolAddress((void**)&wol, g_wol);
    cudaGetSymbolAddress((void**)&qkvh, g_qkvh); cudaGetSymbolAddress((void**)&qkvl, g_qkvl);
    cudaGetSymbolAddress((void**)&ah,  g_ah);   cudaGetSymbolAddress((void**)&al,  g_al);

    cudaFuncSetAttribute(gemm_bf16_kernel<true>,
                         cudaFuncAttributeMaxDynamicSharedMemorySize, GEMM_SMEM);
    cudaFuncSetAttribute(gemm_bf16_kernel<false>,
                         cudaFuncAttributeMaxDynamicSharedMemorySize, GEMM_SMEM);
    cudaFuncSetAttribute(flash_tc_kernel,
                         cudaFuncAttributeMaxDynamicSharedMemorySize, FLASH_SMEM);

    // 0) split prepass
    split_fp32_kernel<<<(Mc * Ec / 4 + 255) / 256, 256>>>(x, xh, xl, Mc * Ec / 4);
    split_fp32_kernel<<<(E3 * Ec / 4 + 255) / 256, 256>>>(qkv_w, wqh, wql, E3 * Ec / 4);
    split_fp32_kernel<<<(Ec * Ec / 4 + 255) / 256, 256>>>(out_w, woh, wol, Ec * Ec / 4);

    // 1) QKV projection -> split qkv
    dim3 g1(E3 / 128, Mc / 128);   // (24, 32)
    gemm_bf16_kernel<true><<<g1, 256, GEMM_SMEM>>>(
        xh, xl, wqh, wql, qkv_b, nullptr, qkvh, qkvl, Mc, E3, Ec);

    // 2) Flash attention -> split attn
    dim3 g2(Sc / 128, Hc, Bc);     // (16, 16, 2)
    flash_tc_kernel<<<g2, 256, FLASH_SMEM>>>(qkvh, qkvl);

    // 3) Output projection -> fp32 out
    dim3 g3(Ec / 128, Mc / 128);   // (8, 32)
    gemm_bf16_kernel<false><<<g3, 256, GEMM_SMEM>>>(
        ah, al, woh, wol, out_b, out, nullptr, nullptr, Mc, Ec, Ec);
}

// round 6
// speedup vs baseline: 3.5773x; 1.3017x over previous
#include <cuda_runtime.h>
#include <cuda_fp16.h>
#include <cstdint>
#include <math.h>

// ===========================================================================
// Problem constants
// ===========================================================================
constexpr int Bc = 2;
constexpr int Sc = 2048;
constexpr int Ec = 1024;
constexpr int Hc = 16;
constexpr int HDc = 64;
constexpr int Mc = Bc * Sc;        // 4096
constexpr int E3 = 3 * Ec;         // 3072

// Scratch (no cudaMalloc allowed) — fp16 hi/lo pairs
__device__ __half g_xh[Mc * Ec],  g_xl[Mc * Ec];
__device__ __half g_wqh[E3 * Ec];            // W rounded (hi only)
__device__ __half g_woh[Ec * Ec];
__device__ __half g_qkvh[Mc * E3], g_qkvl[Mc * E3];
__device__ __half g_ah[Mc * Ec],  g_al[Mc * Ec];

// ===========================================================================
// Helpers
// ===========================================================================
__device__ __forceinline__ uint32_t pack_h2(__half a, __half b) {
    __half2 t = __halves2half2(a, b);       // .x = a (low 16 bits)
    return *reinterpret_cast<uint32_t*>(&t);
}
__device__ __forceinline__ uint32_t smem_u32(const void* p) {
    return (uint32_t)__cvta_generic_to_shared(p);
}
__device__ __forceinline__ void ldm_x4(uint32_t addr, uint32_t r[4]) {
    asm volatile("ldmatrix.sync.aligned.m8n8.x4.shared.b16 {%0,%1,%2,%3}, [%4];"
        : "=r"(r[0]), "=r"(r[1]), "=r"(r[2]), "=r"(r[3]) : "r"(addr));
}
__device__ __forceinline__ void ldm_x4_t(uint32_t addr, uint32_t r[4]) {
    asm volatile("ldmatrix.sync.aligned.m8n8.x4.trans.shared.b16 {%0,%1,%2,%3}, [%4];"
        : "=r"(r[0]), "=r"(r[1]), "=r"(r[2]), "=r"(r[3]) : "r"(addr));
}
__device__ __forceinline__ void mma_f16(float c[4], const uint32_t a[4],
                                        uint32_t b0, uint32_t b1) {
    asm volatile(
        "mma.sync.aligned.m16n8k16.row.col.f32.f16.f16.f32 "
        "{%0,%1,%2,%3}, {%4,%5,%6,%7}, {%8,%9}, {%0,%1,%2,%3};"
        : "+f"(c[0]), "+f"(c[1]), "+f"(c[2]), "+f"(c[3])
        : "r"(a[0]), "r"(a[1]), "r"(a[2]), "r"(a[3]), "r"(b0), "r"(b1));
}
#define CP16(dst, src) \
    asm volatile("cp.async.cg.shared.global [%0], [%1], 16;" :: "r"(dst), "l"(src))
#define CP_COMMIT() asm volatile("cp.async.commit_group;")
#define CP_WAIT0()  asm volatile("cp.async.wait_group 0;")
#define CP_WAIT1()  asm volatile("cp.async.wait_group 1;")

__device__ __forceinline__ void split2h(float v, __half& h, __half& l) {
    h = __float2half(v);
    l = __float2half(v - __half2float(h));
}

// ===========================================================================
// Prepass kernels
// ===========================================================================
__global__ void split_fp32_kernel(const float* __restrict__ src,
                                  __half* __restrict__ hi,
                                  __half* __restrict__ lo, int n4)
{
    int i = blockIdx.x * blockDim.x + threadIdx.x;
    if (i >= n4) return;
    float4 v = reinterpret_cast<const float4*>(src)[i];
    __half h0, h1, h2, h3, l0, l1, l2, l3;
    split2h(v.x, h0, l0); split2h(v.y, h1, l1);
    split2h(v.z, h2, l2); split2h(v.w, h3, l3);
    reinterpret_cast<uint2*>(hi)[i] = make_uint2(pack_h2(h0, h1), pack_h2(h2, h3));
    reinterpret_cast<uint2*>(lo)[i] = make_uint2(pack_h2(l0, l1), pack_h2(l2, l3));
}

__global__ void round_fp32_kernel(const float* __restrict__ src,
                                  __half* __restrict__ hi, int n4)
{
    int i = blockIdx.x * blockDim.x + threadIdx.x;
    if (i >= n4) return;
    float4 v = reinterpret_cast<const float4*>(src)[i];
    reinterpret_cast<uint2*>(hi)[i] = make_uint2(
        pack_h2(__float2half(v.x), __float2half(v.y)),
        pack_h2(__float2half(v.z), __float2half(v.w)));
}

// ===========================================================================
// fp16 GEMM, 2-pass split (Ah*Bh + Al*Bh), cp.async double-buffered.
// CTA 128x128, 8 warps (2Mx4N), warp tile 64x32, K-chunk 32, 2 stages.
// ===========================================================================
constexpr int LDT = 40;                     // padded fp16 leading dim (80B rows)
constexpr int STG = 128 * LDT;              // 5120 elems per tile
constexpr int STAGE3 = 3 * STG;             // Ah, Al, Bh
constexpr int GEMM_SMEM = 2 * STAGE3 * 2;   // 61440 B

template<bool SPLIT_OUT>
__global__ __launch_bounds__(256, 2)
void gemm_f16_kernel(const __half* __restrict__ Ahg, const __half* __restrict__ Alg,
                     const __half* __restrict__ Bhg,
                     const float* __restrict__ bias,
                     float* __restrict__ C,
                     __half* __restrict__ Ch, __half* __restrict__ Cl,
                     int M, int N, int K)
{
    extern __shared__ __half sm[];
    int tid  = threadIdx.x;
    int lane = tid & 31;
    int wid  = tid >> 5;
    int wm   = wid >> 2;
    int wn   = wid & 3;
    int bm   = blockIdx.y * 128;
    int bn   = blockIdx.x * 128;

    int lrow  = lane & 15;
    int lhalf = (lane >> 4) * 8;

    int r0  = tid >> 2;            // 0..63
    int seg = (tid & 3) * 8;       // 0,8,16,24

    const __half* gs0 = Ahg + (size_t)bm * K;
    const __half* gs1 = Alg + (size_t)bm * K;
    const __half* gs2 = Bhg + (size_t)bn * K;

    auto load_stage = [&](int stg, int k0) {
        __half* st = sm + stg * STAGE3;
        const __half* gp[3] = {gs0, gs1, gs2};
        #pragma unroll
        for (int a = 0; a < 3; a++) {
            #pragma unroll
            for (int i = 0; i < 2; i++) {
                int row = r0 + 64 * i;
                CP16(smem_u32(st + a * STG + row * LDT + seg),
                     gp[a] + (size_t)row * K + k0 + seg);
            }
        }
    };

    float acc[4][4][4] = {};

    load_stage(0, 0);
    CP_COMMIT();

    const int nch = K / 32;
    for (int c = 0; c < nch; c++) {
        if (c + 1 < nch) {
            load_stage((c + 1) & 1, (c + 1) * 32);
            CP_COMMIT();
            CP_WAIT1();
        } else {
            CP_WAIT0();
        }
        __syncthreads();

        __half* st = sm + (c & 1) * STAGE3;
        __half* Ah = st;
        __half* Al = st + STG;
        __half* Bh = st + 2 * STG;

        #pragma unroll
        for (int ks = 0; ks < 2; ks++) {
            int kk = ks * 16 + lhalf;

            uint32_t af[4][4];
            uint32_t bhf[2][4];
            #pragma unroll
            for (int mt = 0; mt < 4; mt++)
                ldm_x4(smem_u32(Ah + (wm * 64 + mt * 16 + lrow) * LDT + kk), af[mt]);
            #pragma unroll
            for (int nt = 0; nt < 2; nt++)
                ldm_x4(smem_u32(Bh + (wn * 32 + nt * 16 + lrow) * LDT + kk), bhf[nt]);

            #pragma unroll
            for (int mt = 0; mt < 4; mt++)
                #pragma unroll
                for (int nt = 0; nt < 2; nt++) {
                    mma_f16(acc[mt][nt*2+0], af[mt], bhf[nt][0], bhf[nt][2]);
                    mma_f16(acc[mt][nt*2+1], af[mt], bhf[nt][1], bhf[nt][3]);
                }

            uint32_t alf[4][4];
            #pragma unroll
            for (int mt = 0; mt < 4; mt++)
                ldm_x4(smem_u32(Al + (wm * 64 + mt * 16 + lrow) * LDT + kk), alf[mt]);
            #pragma unroll
            for (int mt = 0; mt < 4; mt++)
                #pragma unroll
                for (int nt = 0; nt < 2; nt++) {
                    mma_f16(acc[mt][nt*2+0], alf[mt], bhf[nt][0], bhf[nt][2]);
                    mma_f16(acc[mt][nt*2+1], alf[mt], bhf[nt][1], bhf[nt][3]);
                }
        }
        __syncthreads();
    }

    // ---- epilogue ----
    #pragma unroll
    for (int mt = 0; mt < 4; mt++) {
        int row = bm + wm * 64 + mt * 16 + (lane >> 2);
        #pragma unroll
        for (int n8 = 0; n8 < 4; n8++) {
            int col = bn + wn * 32 + n8 * 8 + (lane & 3) * 2;
            float b0 = bias[col], b1 = bias[col + 1];
            float v0 = acc[mt][n8][0] + b0, v1 = acc[mt][n8][1] + b1;
            float v2 = acc[mt][n8][2] + b0, v3 = acc[mt][n8][3] + b1;
            if (SPLIT_OUT) {
                __half h0, h1, h2, h3, l0, l1, l2, l3;
                split2h(v0, h0, l0); split2h(v1, h1, l1);
                split2h(v2, h2, l2); split2h(v3, h3, l3);
                *reinterpret_cast<uint32_t*>(Ch + (size_t)row * N + col)       = pack_h2(h0, h1);
                *reinterpret_cast<uint32_t*>(Cl + (size_t)row * N + col)       = pack_h2(l0, l1);
                *reinterpret_cast<uint32_t*>(Ch + (size_t)(row + 8) * N + col) = pack_h2(h2, h3);
                *reinterpret_cast<uint32_t*>(Cl + (size_t)(row + 8) * N + col) = pack_h2(l2, l3);
            } else {
                *reinterpret_cast<float2*>(C + (size_t)row * N + col)       = make_float2(v0, v1);
                *reinterpret_cast<float2*>(C + (size_t)(row + 8) * N + col) = make_float2(v2, v3);
            }
        }
    }
}

// ===========================================================================
// Flash attention (causal), tensor cores.
// QK^T: 3-pass split (score precision).  P·V: 2-pass (P split, V hi).
// CTA: 128 q-rows x one (b,h). 8 warps x 16 q-rows. 64-key tiles, 2 KV stages.
// ===========================================================================
constexpr int LDH = 72;                      // 144B rows, conflict-free
constexpr int FQ  = 128 * LDH;               // 9216 elems per Q tile
constexpr int FKV = 64 * LDH;                // 4608 elems per KV tile
constexpr int KVSTAGE = 3 * FKV;             // Kh, Kl, Vh
constexpr int FLASH_ELEMS = 2 * FQ + 2 * KVSTAGE;   // 46080
constexpr int FLASH_SMEM  = FLASH_ELEMS * 2;        // 92160 B

__global__ __launch_bounds__(256, 2)
void flash_tc_kernel(const __half* __restrict__ qh,
                     const __half* __restrict__ ql)
{
    extern __shared__ __half fs[];
    __half* Qh = fs;
    __half* Ql = fs + FQ;
    __half* KV = fs + 2 * FQ;                 // 2 stages of {Kh, Kl, Vh}

    int tid  = threadIdx.x;
    int lane = tid & 31;
    int wq   = tid >> 5;
    int qt   = gridDim.x - 1 - blockIdx.x;    // heavy q-tiles first
    int h    = blockIdx.y;
    int b    = blockIdx.z;
    int q0   = qt * 128;

    int lrow = lane & 15;
    int lh8  = (lane >> 4) * 8;
    int warp_row_lo = q0 + wq * 16;

    // ---- Q tile loads (cp.async) ----
    {
        #pragma unroll
        for (int i = 0; i < 4; i++) {
            int s   = tid + 256 * i;
            int row = s >> 3;
            int ch  = (s & 7) * 8;
            size_t go = (size_t)(b * Sc + q0 + row) * E3 + h * HDc + ch;
            CP16(smem_u32(Qh + row * LDH + ch), qh + go);
            CP16(smem_u32(Ql + row * LDH + ch), ql + go);
        }
    }

    auto load_kv = [&](int stg, int kc0) {
        __half* st = KV + stg * KVSTAGE;
        #pragma unroll
        for (int i = 0; i < 2; i++) {
            int s   = tid + 256 * i;
            int row = s >> 3;
            int ch  = (s & 7) * 8;
            size_t gk = (size_t)(b * Sc + kc0 + row) * E3 + Ec + h * HDc + ch;
            size_t gv = gk + Ec;
            uint32_t so = row * LDH + ch;
            CP16(smem_u32(st + so),         qh + gk);   // Kh
            CP16(smem_u32(st + FKV + so),   ql + gk);   // Kl
            CP16(smem_u32(st + 2*FKV + so), qh + gv);   // Vh
        }
    };

    load_kv(0, 0);
    CP_COMMIT();

    float o[8][4] = {};
    float mrow[2] = {-1e30f, -1e30f};
    float lsum[2] = {0.f, 0.f};

    const int nkt = 2 * qt + 2;
    for (int kt = 0; kt < nkt; kt++) {
        int kc0 = kt * 64;
        if (kt + 1 < nkt) {
            load_kv((kt + 1) & 1, (kt + 1) * 64);
            CP_COMMIT();
            CP_WAIT1();
        } else {
            CP_WAIT0();
        }
        __syncthreads();

        __half* st = KV + (kt & 1) * KVSTAGE;
        __half* Kh = st;
        __half* Kl = st + FKV;
        __half* Vh = st + 2 * FKV;

        if (kc0 <= warp_row_lo + 15) {
            bool domask = (kc0 + 63 > warp_row_lo);

            // ---- S = Q K^T (3-pass split) ----
            float s[8][4] = {};
            #pragma unroll
            for (int ksj = 0; ksj < 4; ksj++) {
                int kk = ksj * 16 + lh8;
                uint32_t aq[4], al[4];
                ldm_x4(smem_u32(Qh + (wq * 16 + lrow) * LDH + kk), aq);
                ldm_x4(smem_u32(Ql + (wq * 16 + lrow) * LDH + kk), al);
                #pragma unroll
                for (int nt = 0; nt < 4; nt++) {
                    uint32_t kh[4], kl[4];
                    ldm_x4(smem_u32(Kh + (nt * 16 + lrow) * LDH + kk), kh);
                    ldm_x4(smem_u32(Kl + (nt * 16 + lrow) * LDH + kk), kl);
                    mma_f16(s[2*nt+0], aq, kh[0], kh[2]);
                    mma_f16(s[2*nt+1], aq, kh[1], kh[3]);
                    mma_f16(s[2*nt+0], aq, kl[0], kl[2]);
                    mma_f16(s[2*nt+1], aq, kl[1], kl[3]);
                    mma_f16(s[2*nt+0], al, kh[0], kh[2]);
                    mma_f16(s[2*nt+1], al, kh[1], kh[3]);
                }
            }

            // ---- scale + causal mask ----
            int r_lo = warp_row_lo + (lane >> 2);
            #pragma unroll
            for (int n8 = 0; n8 < 8; n8++) {
                int c0 = kc0 + n8 * 8 + (lane & 3) * 2;
                #pragma unroll
                for (int cc = 0; cc < 4; cc++) {
                    float v = s[n8][cc] * 0.125f;
                    if (domask) {
                        int col = c0 + (cc & 1);
                        int row = r_lo + (cc >> 1) * 8;
                        if (col > row) v = -1e30f;
                    }
                    s[n8][cc] = v;
                }
            }

            // ---- online softmax ----
            #pragma unroll
            for (int hh = 0; hh < 2; hh++) {
                float tm = -1e30f;
                #pragma unroll
                for (int n8 = 0; n8 < 8; n8++)
                    tm = fmaxf(tm, fmaxf(s[n8][2*hh], s[n8][2*hh+1]));
                tm = fmaxf(tm, __shfl_xor_sync(0xffffffffu, tm, 1));
                tm = fmaxf(tm, __shfl_xor_sync(0xffffffffu, tm, 2));
                float mn = fmaxf(mrow[hh], tm);
                float corr = __expf(mrow[hh] - mn);
                mrow[hh] = mn;
                float rs = 0.f;
                #pragma unroll
                for (int n8 = 0; n8 < 8; n8++) {
                    s[n8][2*hh]   = __expf(s[n8][2*hh]   - mn);
                    s[n8][2*hh+1] = __expf(s[n8][2*hh+1] - mn);
                    rs += s[n8][2*hh] + s[n8][2*hh+1];
                }
                rs += __shfl_xor_sync(0xffffffffu, rs, 1);
                rs += __shfl_xor_sync(0xffffffffu, rs, 2);
                lsum[hh] = lsum[hh] * corr + rs;
                #pragma unroll
                for (int n8 = 0; n8 < 8; n8++) {
                    o[n8][2*hh]   *= corr;
                    o[n8][2*hh+1] *= corr;
                }
            }

            // ---- O += P V (2-pass: P split, V hi; V via trans ldmatrix) ----
            #pragma unroll
            for (int j = 0; j < 4; j++) {
                uint32_t pA[4], pL[4];
                #pragma unroll
                for (int q2 = 0; q2 < 2; q2++) {
                    const float* sp = s[2*j + q2];
                    #pragma unroll
                    for (int hh = 0; hh < 2; hh++) {
                        __half h0, h1, l0, l1;
                        split2h(sp[2*hh],   h0, l0);
                        split2h(sp[2*hh+1], h1, l1);
                        pA[q2*2 + hh] = pack_h2(h0, h1);
                        pL[q2*2 + hh] = pack_h2(l0, l1);
                    }
                }
                #pragma unroll
                for (int nt = 0; nt < 4; nt++) {
                    uint32_t vh[4];
                    ldm_x4_t(smem_u32(Vh + (j * 16 + lrow) * LDH + nt * 16 + lh8), vh);
                    mma_f16(o[2*nt+0], pA, vh[0], vh[1]);
                    mma_f16(o[2*nt+1], pA, vh[2], vh[3]);
                    mma_f16(o[2*nt+0], pL, vh[0], vh[1]);
                    mma_f16(o[2*nt+1], pL, vh[2], vh[3]);
                }
            }
        }
        __syncthreads();
    }

    // ---- epilogue: normalize, split, write g_ah/g_al ----
    #pragma unroll
    for (int hh = 0; hh < 2; hh++) {
        float inv = 1.0f / lsum[hh];
        int row = warp_row_lo + (lane >> 2) + hh * 8;
        size_t base = (size_t)(b * Sc + row) * Ec + h * HDc;
        #pragma unroll
        for (int n8 = 0; n8 < 8; n8++) {
            int d = n8 * 8 + (lane & 3) * 2;
            float v0 = o[n8][2*hh] * inv;
            float v1 = o[n8][2*hh+1] * inv;
            __half h0, h1, l0, l1;
            split2h(v0, h0, l0); split2h(v1, h1, l1);
            *reinterpret_cast<uint32_t*>(g_ah + base + d) = pack_h2(h0, h1);
            *reinterpret_cast<uint32_t*>(g_al + base + d) = pack_h2(l0, l1);
        }
    }
}

// ===========================================================================
extern "C" void kernel_launch(void* const* d_in, const int* in_sizes, int n_in,
                              void* d_out, int out_size)
{
    const float* x      = (const float*)d_in[0];
    const float* qkv_w  = (const float*)d_in[1];
    const float* qkv_b  = (const float*)d_in[2];
    const float* out_w  = (const float*)d_in[3];
    const float* out_b  = (const float*)d_in[4];
    float* out = (float*)d_out;

    __half *xh, *xl, *wqh, *woh, *qkvh, *qkvl, *ah, *al;
    cudaGetSymbolAddress((void**)&xh,  g_xh);   cudaGetSymbolAddress((void**)&xl,  g_xl);
    cudaGetSymbolAddress((void**)&wqh, g_wqh);  cudaGetSymbolAddress((void**)&woh, g_woh);
    cudaGetSymbolAddress((void**)&qkvh, g_qkvh); cudaGetSymbolAddress((void**)&qkvl, g_qkvl);
    cudaGetSymbolAddress((void**)&ah,  g_ah);   cudaGetSymbolAddress((void**)&al,  g_al);

    cudaFuncSetAttribute(gemm_f16_kernel<true>,
                         cudaFuncAttributeMaxDynamicSharedMemorySize, GEMM_SMEM);
    cudaFuncSetAttribute(gemm_f16_kernel<false>,
                         cudaFuncAttributeMaxDynamicSharedMemorySize, GEMM_SMEM);
    cudaFuncSetAttribute(flash_tc_kernel,
                         cudaFuncAttributeMaxDynamicSharedMemorySize, FLASH_SMEM);

    // 0) prepass: split x; round weights
    split_fp32_kernel<<<(Mc * Ec / 4 + 255) / 256, 256>>>(x, xh, xl, Mc * Ec / 4);
    round_fp32_kernel<<<(E3 * Ec / 4 + 255) / 256, 256>>>(qkv_w, wqh, E3 * Ec / 4);
    round_fp32_kernel<<<(Ec * Ec / 4 + 255) / 256, 256>>>(out_w, woh, Ec * Ec / 4);

    // 1) QKV projection (2-pass) -> split qkv
    dim3 g1(E3 / 128, Mc / 128);   // (24, 32)
    gemm_f16_kernel<true><<<g1, 256, GEMM_SMEM>>>(
        xh, xl, wqh, qkv_b, nullptr, qkvh, qkvl, Mc, E3, Ec);

    // 2) Flash attention -> split attn
    dim3 g2(Sc / 128, Hc, Bc);     // (16, 16, 2)
    flash_tc_kernel<<<g2, 256, FLASH_SMEM>>>(qkvh, qkvl);

    // 3) Output projection (2-pass) -> fp32 out
    dim3 g3(Ec / 128, Mc / 128);   // (8, 32)
    gemm_f16_kernel<false><<<g3, 256, GEMM_SMEM>>>(
        ah, al, woh, out_b, out, nullptr, nullptr, Mc, Ec, Ec);
}

// round 7
// speedup vs baseline: 5.8146x; 1.6254x over previous
#include <cuda_runtime.h>
#include <cuda_fp16.h>
#include <cstdint>
#include <math.h>

// ===========================================================================
// Problem constants
// ===========================================================================
constexpr int Bc = 2;
constexpr int Sc = 2048;
constexpr int Ec = 1024;
constexpr int Hc = 16;
constexpr int HDc = 64;
constexpr int Mc = Bc * Sc;        // 4096
constexpr int E3 = 3 * Ec;         // 3072

// Scratch (no cudaMalloc allowed) — plain fp16 everywhere; P split lives in regs
__device__ __half g_x16[Mc * Ec];
__device__ __half g_wq16[E3 * Ec];
__device__ __half g_wo16[Ec * Ec];
__device__ __half g_qkv16[Mc * E3];
__device__ __half g_attn16[Mc * Ec];

// ===========================================================================
// Helpers
// ===========================================================================
__device__ __forceinline__ uint32_t pack_h2(__half a, __half b) {
    __half2 t = __halves2half2(a, b);       // .x = a (low 16 bits)
    return *reinterpret_cast<uint32_t*>(&t);
}
__device__ __forceinline__ uint32_t smem_u32(const void* p) {
    return (uint32_t)__cvta_generic_to_shared(p);
}
__device__ __forceinline__ void ldm_x4(uint32_t addr, uint32_t r[4]) {
    asm volatile("ldmatrix.sync.aligned.m8n8.x4.shared.b16 {%0,%1,%2,%3}, [%4];"
        : "=r"(r[0]), "=r"(r[1]), "=r"(r[2]), "=r"(r[3]) : "r"(addr));
}
__device__ __forceinline__ void ldm_x4_t(uint32_t addr, uint32_t r[4]) {
    asm volatile("ldmatrix.sync.aligned.m8n8.x4.trans.shared.b16 {%0,%1,%2,%3}, [%4];"
        : "=r"(r[0]), "=r"(r[1]), "=r"(r[2]), "=r"(r[3]) : "r"(addr));
}
__device__ __forceinline__ void mma_f16(float c[4], const uint32_t a[4],
                                        uint32_t b0, uint32_t b1) {
    asm volatile(
        "mma.sync.aligned.m16n8k16.row.col.f32.f16.f16.f32 "
        "{%0,%1,%2,%3}, {%4,%5,%6,%7}, {%8,%9}, {%0,%1,%2,%3};"
        : "+f"(c[0]), "+f"(c[1]), "+f"(c[2]), "+f"(c[3])
        : "r"(a[0]), "r"(a[1]), "r"(a[2]), "r"(a[3]), "r"(b0), "r"(b1));
}
#define CP16(dst, src) \
    asm volatile("cp.async.cg.shared.global [%0], [%1], 16;" :: "r"(dst), "l"(src))
#define CP_COMMIT() asm volatile("cp.async.commit_group;")
#define CP_WAIT0()  asm volatile("cp.async.wait_group 0;")
#define CP_WAIT1()  asm volatile("cp.async.wait_group 1;")

__device__ __forceinline__ void split2h(float v, __half& h, __half& l) {
    h = __float2half(v);
    l = __float2half(v - __half2float(h));
}

// ===========================================================================
// Prepass: round fp32 -> fp16
// ===========================================================================
__global__ void round_fp32_kernel(const float* __restrict__ src,
                                  __half* __restrict__ hi, int n4)
{
    int i = blockIdx.x * blockDim.x + threadIdx.x;
    if (i >= n4) return;
    float4 v = reinterpret_cast<const float4*>(src)[i];
    reinterpret_cast<uint2*>(hi)[i] = make_uint2(
        pack_h2(__float2half(v.x), __float2half(v.y)),
        pack_h2(__float2half(v.z), __float2half(v.w)));
}

// ===========================================================================
// fp16 GEMM, single-pass, cp.async double-buffered.
//   C[M,N] = A[M,K] @ B[N,K]^T + bias
// CTA 128x128, 8 warps (2Mx4N), warp tile 64x32, K-chunk 32, 2 stages.
// HALF_OUT: write rounded fp16 C (for QKV); else fp32 C (final output).
// ===========================================================================
constexpr int LDT = 40;                     // padded fp16 leading dim (80B rows)
constexpr int STG = 128 * LDT;              // 5120 elems per tile
constexpr int STAGE2 = 2 * STG;             // A, B

template<bool HALF_OUT>
__global__ __launch_bounds__(256, 2)
void gemm_f16_kernel(const __half* __restrict__ Ag, const __half* __restrict__ Bg,
                     const float* __restrict__ bias,
                     float* __restrict__ C, __half* __restrict__ Ch,
                     int M, int N, int K)
{
    __shared__ __align__(16) __half sm[2 * STAGE2];   // 40 KB

    int tid  = threadIdx.x;
    int lane = tid & 31;
    int wid  = tid >> 5;
    int wm   = wid >> 2;
    int wn   = wid & 3;
    int bm   = blockIdx.y * 128;
    int bn   = blockIdx.x * 128;

    int lrow  = lane & 15;
    int lhalf = (lane >> 4) * 8;

    int r0  = tid >> 2;            // 0..63
    int seg = (tid & 3) * 8;       // 0,8,16,24

    const __half* gsA = Ag + (size_t)bm * K;
    const __half* gsB = Bg + (size_t)bn * K;

    auto load_stage = [&](int stg, int k0) {
        __half* st = sm + stg * STAGE2;
        #pragma unroll
        for (int i = 0; i < 2; i++) {
            int row = r0 + 64 * i;
            CP16(smem_u32(st + row * LDT + seg),       gsA + (size_t)row * K + k0 + seg);
            CP16(smem_u32(st + STG + row * LDT + seg), gsB + (size_t)row * K + k0 + seg);
        }
    };

    float acc[4][4][4] = {};

    load_stage(0, 0);
    CP_COMMIT();

    const int nch = K / 32;
    for (int c = 0; c < nch; c++) {
        if (c + 1 < nch) {
            load_stage((c + 1) & 1, (c + 1) * 32);
            CP_COMMIT();
            CP_WAIT1();
        } else {
            CP_WAIT0();
        }
        __syncthreads();

        __half* A = sm + (c & 1) * STAGE2;
        __half* B = A + STG;

        #pragma unroll
        for (int ks = 0; ks < 2; ks++) {
            int kk = ks * 16 + lhalf;

            uint32_t af[4][4];
            uint32_t bf[2][4];
            #pragma unroll
            for (int mt = 0; mt < 4; mt++)
                ldm_x4(smem_u32(A + (wm * 64 + mt * 16 + lrow) * LDT + kk), af[mt]);
            #pragma unroll
            for (int nt = 0; nt < 2; nt++)
                ldm_x4(smem_u32(B + (wn * 32 + nt * 16 + lrow) * LDT + kk), bf[nt]);

            #pragma unroll
            for (int mt = 0; mt < 4; mt++)
                #pragma unroll
                for (int nt = 0; nt < 2; nt++) {
                    mma_f16(acc[mt][nt*2+0], af[mt], bf[nt][0], bf[nt][2]);
                    mma_f16(acc[mt][nt*2+1], af[mt], bf[nt][1], bf[nt][3]);
                }
        }
        __syncthreads();
    }

    // ---- epilogue ----
    #pragma unroll
    for (int mt = 0; mt < 4; mt++) {
        int row = bm + wm * 64 + mt * 16 + (lane >> 2);
        #pragma unroll
        for (int n8 = 0; n8 < 4; n8++) {
            int col = bn + wn * 32 + n8 * 8 + (lane & 3) * 2;
            float b0 = bias[col], b1 = bias[col + 1];
            float v0 = acc[mt][n8][0] + b0, v1 = acc[mt][n8][1] + b1;
            float v2 = acc[mt][n8][2] + b0, v3 = acc[mt][n8][3] + b1;
            if (HALF_OUT) {
                *reinterpret_cast<uint32_t*>(Ch + (size_t)row * N + col) =
                    pack_h2(__float2half(v0), __float2half(v1));
                *reinterpret_cast<uint32_t*>(Ch + (size_t)(row + 8) * N + col) =
                    pack_h2(__float2half(v2), __float2half(v3));
            } else {
                *reinterpret_cast<float2*>(C + (size_t)row * N + col)       = make_float2(v0, v1);
                *reinterpret_cast<float2*>(C + (size_t)(row + 8) * N + col) = make_float2(v2, v3);
            }
        }
    }
}

// ===========================================================================
// Flash attention (causal), tensor cores, plain fp16 inputs.
// QK^T: 1-pass (Qh x Kh).  P·V: 2-pass (P split in regs, V rounded).
// CTA: 128 q-rows x one (b,h). 8 warps x 16 q-rows. 64-key tiles, 2 KV stages.
// ===========================================================================
constexpr int LDH = 72;                      // 144B rows, conflict-free
constexpr int FQ  = 128 * LDH;               // 9216 elems (Q tile)
constexpr int FKV = 64 * LDH;                // 4608 elems per tile
constexpr int KVSTAGE = 2 * FKV;             // Kh, Vh
constexpr int FLASH_ELEMS = FQ + 2 * KVSTAGE;       // 27648
constexpr int FLASH_SMEM  = FLASH_ELEMS * 2;        // 55296 B

__global__ __launch_bounds__(256, 2)
void flash_tc_kernel(const __half* __restrict__ qkv)
{
    extern __shared__ __half fs[];
    __half* Qh = fs;
    __half* KV = fs + FQ;                     // 2 stages of {Kh, Vh}

    int tid  = threadIdx.x;
    int lane = tid & 31;
    int wq   = tid >> 5;
    int qt   = gridDim.x - 1 - blockIdx.x;    // heavy q-tiles first
    int h    = blockIdx.y;
    int b    = blockIdx.z;
    int q0   = qt * 128;

    int lrow = lane & 15;
    int lh8  = (lane >> 4) * 8;
    int warp_row_lo = q0 + wq * 16;

    // ---- Q tile loads (cp.async) ----
    {
        #pragma unroll
        for (int i = 0; i < 4; i++) {
            int s   = tid + 256 * i;
            int row = s >> 3;
            int ch  = (s & 7) * 8;
            CP16(smem_u32(Qh + row * LDH + ch),
                 qkv + (size_t)(b * Sc + q0 + row) * E3 + h * HDc + ch);
        }
    }

    auto load_kv = [&](int stg, int kc0) {
        __half* st = KV + stg * KVSTAGE;
        #pragma unroll
        for (int i = 0; i < 2; i++) {
            int s   = tid + 256 * i;
            int row = s >> 3;
            int ch  = (s & 7) * 8;
            size_t gk = (size_t)(b * Sc + kc0 + row) * E3 + Ec + h * HDc + ch;
            uint32_t so = row * LDH + ch;
            CP16(smem_u32(st + so),       qkv + gk);        // Kh
            CP16(smem_u32(st + FKV + so), qkv + gk + Ec);   // Vh
        }
    };

    load_kv(0, 0);
    CP_COMMIT();

    float o[8][4] = {};
    float mrow[2] = {-1e30f, -1e30f};
    float lsum[2] = {0.f, 0.f};

    const int nkt = 2 * qt + 2;
    for (int kt = 0; kt < nkt; kt++) {
        int kc0 = kt * 64;
        if (kt + 1 < nkt) {
            load_kv((kt + 1) & 1, (kt + 1) * 64);
            CP_COMMIT();
            CP_WAIT1();
        } else {
            CP_WAIT0();
        }
        __syncthreads();

        __half* Kh = KV + (kt & 1) * KVSTAGE;
        __half* Vh = Kh + FKV;

        if (kc0 <= warp_row_lo + 15) {
            bool domask = (kc0 + 63 > warp_row_lo);

            // ---- S = Q K^T (1-pass) ----
            float s[8][4] = {};
            #pragma unroll
            for (int ksj = 0; ksj < 4; ksj++) {
                int kk = ksj * 16 + lh8;
                uint32_t aq[4];
                ldm_x4(smem_u32(Qh + (wq * 16 + lrow) * LDH + kk), aq);
                #pragma unroll
                for (int nt = 0; nt < 4; nt++) {
                    uint32_t kh[4];
                    ldm_x4(smem_u32(Kh + (nt * 16 + lrow) * LDH + kk), kh);
                    mma_f16(s[2*nt+0], aq, kh[0], kh[2]);
                    mma_f16(s[2*nt+1], aq, kh[1], kh[3]);
                }
            }

            // ---- scale + causal mask ----
            int r_lo = warp_row_lo + (lane >> 2);
            #pragma unroll
            for (int n8 = 0; n8 < 8; n8++) {
                int c0 = kc0 + n8 * 8 + (lane & 3) * 2;
                #pragma unroll
                for (int cc = 0; cc < 4; cc++) {
                    float v = s[n8][cc] * 0.125f;
                    if (domask) {
                        int col = c0 + (cc & 1);
                        int row = r_lo + (cc >> 1) * 8;
                        if (col > row) v = -1e30f;
                    }
                    s[n8][cc] = v;
                }
            }

            // ---- online softmax ----
            #pragma unroll
            for (int hh = 0; hh < 2; hh++) {
                float tm = -1e30f;
                #pragma unroll
                for (int n8 = 0; n8 < 8; n8++)
                    tm = fmaxf(tm, fmaxf(s[n8][2*hh], s[n8][2*hh+1]));
                tm = fmaxf(tm, __shfl_xor_sync(0xffffffffu, tm, 1));
                tm = fmaxf(tm, __shfl_xor_sync(0xffffffffu, tm, 2));
                float mn = fmaxf(mrow[hh], tm);
                float corr = __expf(mrow[hh] - mn);
                mrow[hh] = mn;
                float rs = 0.f;
                #pragma unroll
                for (int n8 = 0; n8 < 8; n8++) {
                    s[n8][2*hh]   = __expf(s[n8][2*hh]   - mn);
                    s[n8][2*hh+1] = __expf(s[n8][2*hh+1] - mn);
                    rs += s[n8][2*hh] + s[n8][2*hh+1];
                }
                rs += __shfl_xor_sync(0xffffffffu, rs, 1);
                rs += __shfl_xor_sync(0xffffffffu, rs, 2);
                lsum[hh] = lsum[hh] * corr + rs;
                #pragma unroll
                for (int n8 = 0; n8 < 8; n8++) {
                    o[n8][2*hh]   *= corr;
                    o[n8][2*hh+1] *= corr;
                }
            }

            // ---- O += P V (2-pass: P split, V rounded; V via trans ldmatrix) ----
            #pragma unroll
            for (int j = 0; j < 4; j++) {
                uint32_t pA[4], pL[4];
                #pragma unroll
                for (int q2 = 0; q2 < 2; q2++) {
                    const float* sp = s[2*j + q2];
                    #pragma unroll
                    for (int hh = 0; hh < 2; hh++) {
                        __half h0, h1, l0, l1;
                        split2h(sp[2*hh],   h0, l0);
                        split2h(sp[2*hh+1], h1, l1);
                        pA[q2*2 + hh] = pack_h2(h0, h1);
                        pL[q2*2 + hh] = pack_h2(l0, l1);
                    }
                }
                #pragma unroll
                for (int nt = 0; nt < 4; nt++) {
                    uint32_t vh[4];
                    ldm_x4_t(smem_u32(Vh + (j * 16 + lrow) * LDH + nt * 16 + lh8), vh);
                    mma_f16(o[2*nt+0], pA, vh[0], vh[1]);
                    mma_f16(o[2*nt+1], pA, vh[2], vh[3]);
                    mma_f16(o[2*nt+0], pL, vh[0], vh[1]);
                    mma_f16(o[2*nt+1], pL, vh[2], vh[3]);
                }
            }
        }
        __syncthreads();
    }

    // ---- epilogue: normalize, round, write fp16 attn ----
    #pragma unroll
    for (int hh = 0; hh < 2; hh++) {
        float inv = 1.0f / lsum[hh];
        int row = warp_row_lo + (lane >> 2) + hh * 8;
        size_t base = (size_t)(b * Sc + row) * Ec + h * HDc;
        #pragma unroll
        for (int n8 = 0; n8 < 8; n8++) {
            int d = n8 * 8 + (lane & 3) * 2;
            *reinterpret_cast<uint32_t*>(g_attn16 + base + d) =
                pack_h2(__float2half(o[n8][2*hh] * inv),
                        __float2half(o[n8][2*hh+1] * inv));
        }
    }
}

// ===========================================================================
extern "C" void kernel_launch(void* const* d_in, const int* in_sizes, int n_in,
                              void* d_out, int out_size)
{
    const float* x      = (const float*)d_in[0];
    const float* qkv_w  = (const float*)d_in[1];
    const float* qkv_b  = (const float*)d_in[2];
    const float* out_w  = (const float*)d_in[3];
    const float* out_b  = (const float*)d_in[4];
    float* out = (float*)d_out;

    __half *x16, *wq16, *wo16, *qkv16, *a16;
    cudaGetSymbolAddress((void**)&x16,   g_x16);
    cudaGetSymbolAddress((void**)&wq16,  g_wq16);
    cudaGetSymbolAddress((void**)&wo16,  g_wo16);
    cudaGetSymbolAddress((void**)&qkv16, g_qkv16);
    cudaGetSymbolAddress((void**)&a16,   g_attn16);

    cudaFuncSetAttribute(flash_tc_kernel,
                         cudaFuncAttributeMaxDynamicSharedMemorySize, FLASH_SMEM);

    // 0) prepass: round x and weights to fp16
    round_fp32_kernel<<<(Mc * Ec / 4 + 255) / 256, 256>>>(x, x16, Mc * Ec / 4);
    round_fp32_kernel<<<(E3 * Ec / 4 + 255) / 256, 256>>>(qkv_w, wq16, E3 * Ec / 4);
    round_fp32_kernel<<<(Ec * Ec / 4 + 255) / 256, 256>>>(out_w, wo16, Ec * Ec / 4);

    // 1) QKV projection (1-pass) -> fp16 qkv
    dim3 g1(E3 / 128, Mc / 128);   // (24, 32)
    gemm_f16_kernel<true><<<g1, 256>>>(x16, wq16, qkv_b, nullptr, qkv16, Mc, E3, Ec);

    // 2) Flash attention -> fp16 attn
    dim3 g2(Sc / 128, Hc, Bc);     // (16, 16, 2)
    flash_tc_kernel<<<g2, 256, FLASH_SMEM>>>(qkv16);

    // 3) Output projection (1-pass) -> fp32 out
    dim3 g3(Ec / 128, Mc / 128);   // (8, 32)
    gemm_f16_kernel<false><<<g3, 256>>>(a16, wo16, out_b, out, nullptr, Mc, Ec, Ec);
}

// round 8
// speedup vs baseline: 6.4121x; 1.1028x over previous
#include <cuda_runtime.h>
#include <cuda_fp16.h>
#include <cstdint>
#include <math.h>

// ===========================================================================
// Problem constants
// ===========================================================================
constexpr int Bc = 2;
constexpr int Sc = 2048;
constexpr int Ec = 1024;
constexpr int Hc = 16;
constexpr int HDc = 64;
constexpr int Mc = Bc * Sc;        // 4096
constexpr int E3 = 3 * Ec;         // 3072

// Scratch (no cudaMalloc allowed)
__device__ __half g_x16[Mc * Ec];
__device__ __half g_wq16[E3 * Ec];
__device__ __half g_wo16[Ec * Ec];
__device__ __half g_qkv16[Mc * E3];
__device__ __half g_attn16[Mc * Ec];

// ===========================================================================
// Helpers
// ===========================================================================
__device__ __forceinline__ uint32_t pack_h2(__half a, __half b) {
    __half2 t = __halves2half2(a, b);       // .x = a (low 16 bits)
    return *reinterpret_cast<uint32_t*>(&t);
}
__device__ __forceinline__ uint32_t pack_f2(float a, float b) {
    __half2 t = __float22half2_rn(make_float2(a, b));
    return *reinterpret_cast<uint32_t*>(&t);
}
__device__ __forceinline__ uint32_t smem_u32(const void* p) {
    return (uint32_t)__cvta_generic_to_shared(p);
}
__device__ __forceinline__ void ldm_x4(uint32_t addr, uint32_t r[4]) {
    asm volatile("ldmatrix.sync.aligned.m8n8.x4.shared.b16 {%0,%1,%2,%3}, [%4];"
        : "=r"(r[0]), "=r"(r[1]), "=r"(r[2]), "=r"(r[3]) : "r"(addr));
}
__device__ __forceinline__ void ldm_x4_t(uint32_t addr, uint32_t r[4]) {
    asm volatile("ldmatrix.sync.aligned.m8n8.x4.trans.shared.b16 {%0,%1,%2,%3}, [%4];"
        : "=r"(r[0]), "=r"(r[1]), "=r"(r[2]), "=r"(r[3]) : "r"(addr));
}
__device__ __forceinline__ void mma_f16(float c[4], const uint32_t a[4],
                                        uint32_t b0, uint32_t b1) {
    asm volatile(
        "mma.sync.aligned.m16n8k16.row.col.f32.f16.f16.f32 "
        "{%0,%1,%2,%3}, {%4,%5,%6,%7}, {%8,%9}, {%0,%1,%2,%3};"
        : "+f"(c[0]), "+f"(c[1]), "+f"(c[2]), "+f"(c[3])
        : "r"(a[0]), "r"(a[1]), "r"(a[2]), "r"(a[3]), "r"(b0), "r"(b1));
}
#define CP16(dst, src) \
    asm volatile("cp.async.cg.shared.global [%0], [%1], 16;" :: "r"(dst), "l"(src))
#define CP_COMMIT() asm volatile("cp.async.commit_group;")
#define CP_WAIT0()  asm volatile("cp.async.wait_group 0;")
#define CP_WAIT1()  asm volatile("cp.async.wait_group 1;")

// ===========================================================================
// Prepass: round fp32 -> fp16
// ===========================================================================
__global__ void round_fp32_kernel(const float* __restrict__ src,
                                  __half* __restrict__ hi, int n4)
{
    int i = blockIdx.x * blockDim.x + threadIdx.x;
    if (i >= n4) return;
    float4 v = reinterpret_cast<const float4*>(src)[i];
    reinterpret_cast<uint2*>(hi)[i] = make_uint2(pack_f2(v.x, v.y), pack_f2(v.z, v.w));
}

// ===========================================================================
// fp16 GEMM, single-pass, cp.async double-buffered.  (unchanged from R7)
// CTA 128x128, 8 warps (2Mx4N), warp tile 64x32, K-chunk 32, 2 stages.
// ===========================================================================
constexpr int LDT = 40;
constexpr int STG = 128 * LDT;
constexpr int STAGE2 = 2 * STG;

template<bool HALF_OUT>
__global__ __launch_bounds__(256, 2)
void gemm_f16_kernel(const __half* __restrict__ Ag, const __half* __restrict__ Bg,
                     const float* __restrict__ bias,
                     float* __restrict__ C, __half* __restrict__ Ch,
                     int M, int N, int K)
{
    __shared__ __align__(16) __half sm[2 * STAGE2];   // 40 KB

    int tid  = threadIdx.x;
    int lane = tid & 31;
    int wid  = tid >> 5;
    int wm   = wid >> 2;
    int wn   = wid & 3;
    int bm   = blockIdx.y * 128;
    int bn   = blockIdx.x * 128;

    int lrow  = lane & 15;
    int lhalf = (lane >> 4) * 8;

    int r0  = tid >> 2;
    int seg = (tid & 3) * 8;

    const __half* gsA = Ag + (size_t)bm * K;
    const __half* gsB = Bg + (size_t)bn * K;

    auto load_stage = [&](int stg, int k0) {
        __half* st = sm + stg * STAGE2;
        #pragma unroll
        for (int i = 0; i < 2; i++) {
            int row = r0 + 64 * i;
            CP16(smem_u32(st + row * LDT + seg),       gsA + (size_t)row * K + k0 + seg);
            CP16(smem_u32(st + STG + row * LDT + seg), gsB + (size_t)row * K + k0 + seg);
        }
    };

    float acc[4][4][4] = {};

    load_stage(0, 0);
    CP_COMMIT();

    const int nch = K / 32;
    for (int c = 0; c < nch; c++) {
        if (c + 1 < nch) {
            load_stage((c + 1) & 1, (c + 1) * 32);
            CP_COMMIT();
            CP_WAIT1();
        } else {
            CP_WAIT0();
        }
        __syncthreads();

        __half* A = sm + (c & 1) * STAGE2;
        __half* B = A + STG;

        #pragma unroll
        for (int ks = 0; ks < 2; ks++) {
            int kk = ks * 16 + lhalf;

            uint32_t af[4][4];
            uint32_t bf[2][4];
            #pragma unroll
            for (int mt = 0; mt < 4; mt++)
                ldm_x4(smem_u32(A + (wm * 64 + mt * 16 + lrow) * LDT + kk), af[mt]);
            #pragma unroll
            for (int nt = 0; nt < 2; nt++)
                ldm_x4(smem_u32(B + (wn * 32 + nt * 16 + lrow) * LDT + kk), bf[nt]);

            #pragma unroll
            for (int mt = 0; mt < 4; mt++)
                #pragma unroll
                for (int nt = 0; nt < 2; nt++) {
                    mma_f16(acc[mt][nt*2+0], af[mt], bf[nt][0], bf[nt][2]);
                    mma_f16(acc[mt][nt*2+1], af[mt], bf[nt][1], bf[nt][3]);
                }
        }
        __syncthreads();
    }

    #pragma unroll
    for (int mt = 0; mt < 4; mt++) {
        int row = bm + wm * 64 + mt * 16 + (lane >> 2);
        #pragma unroll
        for (int n8 = 0; n8 < 4; n8++) {
            int col = bn + wn * 32 + n8 * 8 + (lane & 3) * 2;
            float b0 = bias[col], b1 = bias[col + 1];
            float v0 = acc[mt][n8][0] + b0, v1 = acc[mt][n8][1] + b1;
            float v2 = acc[mt][n8][2] + b0, v3 = acc[mt][n8][3] + b1;
            if (HALF_OUT) {
                *reinterpret_cast<uint32_t*>(Ch + (size_t)row * N + col)       = pack_f2(v0, v1);
                *reinterpret_cast<uint32_t*>(Ch + (size_t)(row + 8) * N + col) = pack_f2(v2, v3);
            } else {
                *reinterpret_cast<float2*>(C + (size_t)row * N + col)       = make_float2(v0, v1);
                *reinterpret_cast<float2*>(C + (size_t)(row + 8) * N + col) = make_float2(v2, v3);
            }
        }
    }
}

// ===========================================================================
// Flash attention (causal), tensor cores, plain fp16.
// QK^T: 1-pass.  P·V: 1-pass (P rounded to fp16 in regs).
// CTA: 128 q-rows x one (b,h). 8 warps x 16 q-rows. 64-key tiles, 2 KV stages.
// ===========================================================================
constexpr int LDH = 72;
constexpr int FQ  = 128 * LDH;
constexpr int FKV = 64 * LDH;
constexpr int KVSTAGE = 2 * FKV;
constexpr int FLASH_ELEMS = FQ + 2 * KVSTAGE;
constexpr int FLASH_SMEM  = FLASH_ELEMS * 2;        // 55296 B

__global__ __launch_bounds__(256, 2)
void flash_tc_kernel(const __half* __restrict__ qkv)
{
    extern __shared__ __half fs[];
    __half* Qh = fs;
    __half* KV = fs + FQ;

    int tid  = threadIdx.x;
    int lane = tid & 31;
    int wq   = tid >> 5;
    int qt   = gridDim.x - 1 - blockIdx.x;    // heavy q-tiles first
    int h    = blockIdx.y;
    int b    = blockIdx.z;
    int q0   = qt * 128;

    int lrow = lane & 15;
    int lh8  = (lane >> 4) * 8;
    int warp_row_lo = q0 + wq * 16;

    {
        #pragma unroll
        for (int i = 0; i < 4; i++) {
            int s   = tid + 256 * i;
            int row = s >> 3;
            int ch  = (s & 7) * 8;
            CP16(smem_u32(Qh + row * LDH + ch),
                 qkv + (size_t)(b * Sc + q0 + row) * E3 + h * HDc + ch);
        }
    }

    auto load_kv = [&](int stg, int kc0) {
        __half* st = KV + stg * KVSTAGE;
        #pragma unroll
        for (int i = 0; i < 2; i++) {
            int s   = tid + 256 * i;
            int row = s >> 3;
            int ch  = (s & 7) * 8;
            size_t gk = (size_t)(b * Sc + kc0 + row) * E3 + Ec + h * HDc + ch;
            uint32_t so = row * LDH + ch;
            CP16(smem_u32(st + so),       qkv + gk);        // Kh
            CP16(smem_u32(st + FKV + so), qkv + gk + Ec);   // Vh
        }
    };

    load_kv(0, 0);
    CP_COMMIT();

    float o[8][4] = {};
    float mrow[2] = {-1e30f, -1e30f};
    float lsum[2] = {0.f, 0.f};

    const int nkt = 2 * qt + 2;
    for (int kt = 0; kt < nkt; kt++) {
        int kc0 = kt * 64;
        if (kt + 1 < nkt) {
            load_kv((kt + 1) & 1, (kt + 1) * 64);
            CP_COMMIT();
            CP_WAIT1();
        } else {
            CP_WAIT0();
        }
        __syncthreads();

        __half* Kh = KV + (kt & 1) * KVSTAGE;
        __half* Vh = Kh + FKV;

        if (kc0 <= warp_row_lo + 15) {
            bool domask = (kc0 + 63 > warp_row_lo);

            // ---- S = Q K^T (1-pass) ----
            float s[8][4] = {};
            #pragma unroll
            for (int ksj = 0; ksj < 4; ksj++) {
                int kk = ksj * 16 + lh8;
                uint32_t aq[4];
                ldm_x4(smem_u32(Qh + (wq * 16 + lrow) * LDH + kk), aq);
                #pragma unroll
                for (int nt = 0; nt < 4; nt++) {
                    uint32_t kh[4];
                    ldm_x4(smem_u32(Kh + (nt * 16 + lrow) * LDH + kk), kh);
                    mma_f16(s[2*nt+0], aq, kh[0], kh[2]);
                    mma_f16(s[2*nt+1], aq, kh[1], kh[3]);
                }
            }

            // ---- scale + causal mask ----
            int r_lo = warp_row_lo + (lane >> 2);
            #pragma unroll
            for (int n8 = 0; n8 < 8; n8++) {
                int c0 = kc0 + n8 * 8 + (lane & 3) * 2;
                #pragma unroll
                for (int cc = 0; cc < 4; cc++) {
                    float v = s[n8][cc] * 0.125f;
                    if (domask) {
                        int col = c0 + (cc & 1);
                        int row = r_lo + (cc >> 1) * 8;
                        if (col > row) v = -1e30f;
                    }
                    s[n8][cc] = v;
                }
            }

            // ---- online softmax ----
            #pragma unroll
            for (int hh = 0; hh < 2; hh++) {
                float tm = -1e30f;
                #pragma unroll
                for (int n8 = 0; n8 < 8; n8++)
                    tm = fmaxf(tm, fmaxf(s[n8][2*hh], s[n8][2*hh+1]));
                tm = fmaxf(tm, __shfl_xor_sync(0xffffffffu, tm, 1));
                tm = fmaxf(tm, __shfl_xor_sync(0xffffffffu, tm, 2));
                float mn = fmaxf(mrow[hh], tm);
                float corr = __expf(mrow[hh] - mn);
                mrow[hh] = mn;
                float rs = 0.f;
                #pragma unroll
                for (int n8 = 0; n8 < 8; n8++) {
                    s[n8][2*hh]   = __expf(s[n8][2*hh]   - mn);
                    s[n8][2*hh+1] = __expf(s[n8][2*hh+1] - mn);
                    rs += s[n8][2*hh] + s[n8][2*hh+1];
                }
                rs += __shfl_xor_sync(0xffffffffu, rs, 1);
                rs += __shfl_xor_sync(0xffffffffu, rs, 2);
                lsum[hh] = lsum[hh] * corr + rs;
                #pragma unroll
                for (int n8 = 0; n8 < 8; n8++) {
                    o[n8][2*hh]   *= corr;
                    o[n8][2*hh+1] *= corr;
                }
            }

            // ---- O += P V (1-pass: P rounded; V via trans ldmatrix) ----
            #pragma unroll
            for (int j = 0; j < 4; j++) {
                uint32_t pA[4];
                #pragma unroll
                for (int q2 = 0; q2 < 2; q2++) {
                    const float* sp = s[2*j + q2];
                    pA[q2*2 + 0] = pack_f2(sp[0], sp[1]);
                    pA[q2*2 + 1] = pack_f2(sp[2], sp[3]);
                }
                #pragma unroll
                for (int nt = 0; nt < 4; nt++) {
                    uint32_t vh[4];
                    ldm_x4_t(smem_u32(Vh + (j * 16 + lrow) * LDH + nt * 16 + lh8), vh);
                    mma_f16(o[2*nt+0], pA, vh[0], vh[1]);
                    mma_f16(o[2*nt+1], pA, vh[2], vh[3]);
                }
            }
        }
        __syncthreads();
    }

    // ---- epilogue: normalize, round, write fp16 attn ----
    #pragma unroll
    for (int hh = 0; hh < 2; hh++) {
        float inv = 1.0f / lsum[hh];
        int row = warp_row_lo + (lane >> 2) + hh * 8;
        size_t base = (size_t)(b * Sc + row) * Ec + h * HDc;
        #pragma unroll
        for (int n8 = 0; n8 < 8; n8++) {
            int d = n8 * 8 + (lane & 3) * 2;
            *reinterpret_cast<uint32_t*>(g_attn16 + base + d) =
                pack_f2(o[n8][2*hh] * inv, o[n8][2*hh+1] * inv);
        }
    }
}

// ===========================================================================
extern "C" void kernel_launch(void* const* d_in, const int* in_sizes, int n_in,
                              void* d_out, int out_size)
{
    const float* x      = (const float*)d_in[0];
    const float* qkv_w  = (const float*)d_in[1];
    const float* qkv_b  = (const float*)d_in[2];
    const float* out_w  = (const float*)d_in[3];
    const float* out_b  = (const float*)d_in[4];
    float* out = (float*)d_out;

    __half *x16, *wq16, *wo16, *qkv16, *a16;
    cudaGetSymbolAddress((void**)&x16,   g_x16);
    cudaGetSymbolAddress((void**)&wq16,  g_wq16);
    cudaGetSymbolAddress((void**)&wo16,  g_wo16);
    cudaGetSymbolAddress((void**)&qkv16, g_qkv16);
    cudaGetSymbolAddress((void**)&a16,   g_attn16);

    cudaFuncSetAttribute(flash_tc_kernel,
                         cudaFuncAttributeMaxDynamicSharedMemorySize, FLASH_SMEM);

    // 0) prepass: round x and weights to fp16
    round_fp32_kernel<<<(Mc * Ec / 4 + 255) / 256, 256>>>(x, x16, Mc * Ec / 4);
    round_fp32_kernel<<<(E3 * Ec / 4 + 255) / 256, 256>>>(qkv_w, wq16, E3 * Ec / 4);
    round_fp32_kernel<<<(Ec * Ec / 4 + 255) / 256, 256>>>(out_w, wo16, Ec * Ec / 4);

    // 1) QKV projection (1-pass) -> fp16 qkv
    dim3 g1(E3 / 128, Mc / 128);   // (24, 32)
    gemm_f16_kernel<true><<<g1, 256>>>(x16, wq16, qkv_b, nullptr, qkv16, Mc, E3, Ec);

    // 2) Flash attention -> fp16 attn
    dim3 g2(Sc / 128, Hc, Bc);     // (16, 16, 2)
    flash_tc_kernel<<<g2, 256, FLASH_SMEM>>>(qkv16);

    // 3) Output projection (1-pass) -> fp32 out
    dim3 g3(Ec / 128, Mc / 128);   // (8, 32)
    gemm_f16_kernel<false><<<g3, 256>>>(a16, wo16, out_b, out, nullptr, Mc, Ec, Ec);
}

// round 9
// speedup vs baseline: 6.7456x; 1.0520x over previous
#include <cuda_runtime.h>
#include <cuda_fp16.h>
#include <cstdint>
#include <math.h>

// ===========================================================================
// Problem constants
// ===========================================================================
constexpr int Bc = 2;
constexpr int Sc = 2048;
constexpr int Ec = 1024;
constexpr int Hc = 16;
constexpr int HDc = 64;
constexpr int Mc = Bc * Sc;        // 4096
constexpr int E3 = 3 * Ec;         // 3072

// Scratch (no cudaMalloc allowed)
__device__ __half g_x16[Mc * Ec];
__device__ __half g_wq16[E3 * Ec];
__device__ __half g_wo16[Ec * Ec];
__device__ __half g_qkv16[Mc * E3];
__device__ __half g_attn16[Mc * Ec];

// ===========================================================================
// Helpers
// ===========================================================================
__device__ __forceinline__ uint32_t pack_f2(float a, float b) {
    __half2 t = __float22half2_rn(make_float2(a, b));
    return *reinterpret_cast<uint32_t*>(&t);
}
__device__ __forceinline__ uint32_t smem_u32(const void* p) {
    return (uint32_t)__cvta_generic_to_shared(p);
}
__device__ __forceinline__ void ldm_x4(uint32_t addr, uint32_t r[4]) {
    asm volatile("ldmatrix.sync.aligned.m8n8.x4.shared.b16 {%0,%1,%2,%3}, [%4];"
        : "=r"(r[0]), "=r"(r[1]), "=r"(r[2]), "=r"(r[3]) : "r"(addr));
}
__device__ __forceinline__ void ldm_x4_t(uint32_t addr, uint32_t r[4]) {
    asm volatile("ldmatrix.sync.aligned.m8n8.x4.trans.shared.b16 {%0,%1,%2,%3}, [%4];"
        : "=r"(r[0]), "=r"(r[1]), "=r"(r[2]), "=r"(r[3]) : "r"(addr));
}
__device__ __forceinline__ void mma_f16(float c[4], const uint32_t a[4],
                                        uint32_t b0, uint32_t b1) {
    asm volatile(
        "mma.sync.aligned.m16n8k16.row.col.f32.f16.f16.f32 "
        "{%0,%1,%2,%3}, {%4,%5,%6,%7}, {%8,%9}, {%0,%1,%2,%3};"
        : "+f"(c[0]), "+f"(c[1]), "+f"(c[2]), "+f"(c[3])
        : "r"(a[0]), "r"(a[1]), "r"(a[2]), "r"(a[3]), "r"(b0), "r"(b1));
}
#define CP16(dst, src) \
    asm volatile("cp.async.cg.shared.global [%0], [%1], 16;" :: "r"(dst), "l"(src))
#define CP_COMMIT() asm volatile("cp.async.commit_group;")
#define CP_WAIT0()  asm volatile("cp.async.wait_group 0;")
#define CP_WAIT1()  asm volatile("cp.async.wait_group 1;")

// ===========================================================================
// Prepass: round x, qkv_w, out_w fp32 -> fp16 in ONE kernel
// ===========================================================================
constexpr int NX4  = Mc * Ec / 4;   // 1048576
constexpr int NWQ4 = E3 * Ec / 4;   //  786432
constexpr int NWO4 = Ec * Ec / 4;   //  262144
constexpr int NALL4 = NX4 + NWQ4 + NWO4;

__global__ void round_all_kernel(const float* __restrict__ x,
                                 const float* __restrict__ wq,
                                 const float* __restrict__ wo,
                                 __half* __restrict__ x16,
                                 __half* __restrict__ wq16,
                                 __half* __restrict__ wo16)
{
    int i = blockIdx.x * blockDim.x + threadIdx.x;
    const float* src; __half* dst; int j;
    if (i < NX4)                 { src = x;  dst = x16;  j = i; }
    else if (i < NX4 + NWQ4)     { src = wq; dst = wq16; j = i - NX4; }
    else if (i < NALL4)          { src = wo; dst = wo16; j = i - NX4 - NWQ4; }
    else return;
    float4 v = reinterpret_cast<const float4*>(src)[j];
    reinterpret_cast<uint2*>(dst)[j] = make_uint2(pack_f2(v.x, v.y), pack_f2(v.z, v.w));
}

// ===========================================================================
// fp16 GEMM, single-pass, 3-stage cp.async pipeline, one sync per chunk.
// CTA 128x128, 8 warps (2Mx4N), warp tile 64x32, K-chunk 32.
// ===========================================================================
constexpr int LDT = 40;
constexpr int STG = 128 * LDT;              // 5120 elems per tile
constexpr int STAGE2 = 2 * STG;             // A+B per stage
constexpr int GEMM_SMEM = 3 * STAGE2 * 2;   // 61440 B

template<bool HALF_OUT>
__global__ __launch_bounds__(256, 2)
void gemm_f16_kernel(const __half* __restrict__ Ag, const __half* __restrict__ Bg,
                     const float* __restrict__ bias,
                     float* __restrict__ C, __half* __restrict__ Ch,
                     int M, int N, int K)
{
    extern __shared__ __half sm[];

    int tid  = threadIdx.x;
    int lane = tid & 31;
    int wid  = tid >> 5;
    int wm   = wid >> 2;
    int wn   = wid & 3;
    int bm   = blockIdx.y * 128;
    int bn   = blockIdx.x * 128;

    int lrow  = lane & 15;
    int lhalf = (lane >> 4) * 8;

    int r0  = tid >> 2;
    int seg = (tid & 3) * 8;

    const __half* gsA = Ag + (size_t)bm * K;
    const __half* gsB = Bg + (size_t)bn * K;

    auto load_stage = [&](int stg, int k0) {
        __half* st = sm + stg * STAGE2;
        #pragma unroll
        for (int i = 0; i < 2; i++) {
            int row = r0 + 64 * i;
            CP16(smem_u32(st + row * LDT + seg),       gsA + (size_t)row * K + k0 + seg);
            CP16(smem_u32(st + STG + row * LDT + seg), gsB + (size_t)row * K + k0 + seg);
        }
    };

    float acc[4][4][4] = {};

    load_stage(0, 0);  CP_COMMIT();
    load_stage(1, 32); CP_COMMIT();

    const int nch = K / 32;   // 32
    int slot = 0;
    for (int c = 0; c < nch; c++) {
        CP_WAIT1();          // stage c complete
        __syncthreads();     // all readers of stage c-1 done -> slot (c+2)%3 free

        if (c + 2 < nch) load_stage((c + 2) % 3, (c + 2) * 32);
        CP_COMMIT();         // empty group on tail keeps count invariant

        __half* A = sm + slot * STAGE2;
        __half* B = A + STG;
        slot = (slot == 2) ? 0 : slot + 1;

        #pragma unroll
        for (int ks = 0; ks < 2; ks++) {
            int kk = ks * 16 + lhalf;

            uint32_t af[4][4];
            uint32_t bf[2][4];
            #pragma unroll
            for (int mt = 0; mt < 4; mt++)
                ldm_x4(smem_u32(A + (wm * 64 + mt * 16 + lrow) * LDT + kk), af[mt]);
            #pragma unroll
            for (int nt = 0; nt < 2; nt++)
                ldm_x4(smem_u32(B + (wn * 32 + nt * 16 + lrow) * LDT + kk), bf[nt]);

            #pragma unroll
            for (int mt = 0; mt < 4; mt++)
                #pragma unroll
                for (int nt = 0; nt < 2; nt++) {
                    mma_f16(acc[mt][nt*2+0], af[mt], bf[nt][0], bf[nt][2]);
                    mma_f16(acc[mt][nt*2+1], af[mt], bf[nt][1], bf[nt][3]);
                }
        }
    }

    #pragma unroll
    for (int mt = 0; mt < 4; mt++) {
        int row = bm + wm * 64 + mt * 16 + (lane >> 2);
        #pragma unroll
        for (int n8 = 0; n8 < 4; n8++) {
            int col = bn + wn * 32 + n8 * 8 + (lane & 3) * 2;
            float b0 = bias[col], b1 = bias[col + 1];
            float v0 = acc[mt][n8][0] + b0, v1 = acc[mt][n8][1] + b1;
            float v2 = acc[mt][n8][2] + b0, v3 = acc[mt][n8][3] + b1;
            if (HALF_OUT) {
                *reinterpret_cast<uint32_t*>(Ch + (size_t)row * N + col)       = pack_f2(v0, v1);
                *reinterpret_cast<uint32_t*>(Ch + (size_t)(row + 8) * N + col) = pack_f2(v2, v3);
            } else {
                *reinterpret_cast<float2*>(C + (size_t)row * N + col)       = make_float2(v0, v1);
                *reinterpret_cast<float2*>(C + (size_t)(row + 8) * N + col) = make_float2(v2, v3);
            }
        }
    }
}

// ===========================================================================
// Flash attention (causal), tensor cores, plain fp16.
// QK^T 1-pass; P·V 1-pass. 3-stage KV cp.async pipeline, one sync per tile.
// CTA: 128 q-rows x one (b,h). 8 warps x 16 q-rows. 64-key tiles.
// ===========================================================================
constexpr int LDH = 72;
constexpr int FQ  = 128 * LDH;               // 9216
constexpr int FKV = 64 * LDH;                // 4608
constexpr int KVSTAGE = 2 * FKV;             // Kh, Vh = 9216
constexpr int FLASH_ELEMS = FQ + 3 * KVSTAGE;       // 36864
constexpr int FLASH_SMEM  = FLASH_ELEMS * 2;        // 73728 B

__global__ __launch_bounds__(256, 2)
void flash_tc_kernel(const __half* __restrict__ qkv)
{
    extern __shared__ __half fs[];
    __half* Qh = fs;
    __half* KV = fs + FQ;

    int tid  = threadIdx.x;
    int lane = tid & 31;
    int wq   = tid >> 5;
    int qt   = gridDim.x - 1 - blockIdx.x;    // heavy q-tiles first
    int h    = blockIdx.y;
    int b    = blockIdx.z;
    int q0   = qt * 128;

    int lrow = lane & 15;
    int lh8  = (lane >> 4) * 8;
    int warp_row_lo = q0 + wq * 16;

    {
        #pragma unroll
        for (int i = 0; i < 4; i++) {
            int s   = tid + 256 * i;
            int row = s >> 3;
            int ch  = (s & 7) * 8;
            CP16(smem_u32(Qh + row * LDH + ch),
                 qkv + (size_t)(b * Sc + q0 + row) * E3 + h * HDc + ch);
        }
    }

    auto load_kv = [&](int stg, int kc0) {
        __half* st = KV + stg * KVSTAGE;
        #pragma unroll
        for (int i = 0; i < 2; i++) {
            int s   = tid + 256 * i;
            int row = s >> 3;
            int ch  = (s & 7) * 8;
            size_t gk = (size_t)(b * Sc + kc0 + row) * E3 + Ec + h * HDc + ch;
            uint32_t so = row * LDH + ch;
            CP16(smem_u32(st + so),       qkv + gk);        // Kh
            CP16(smem_u32(st + FKV + so), qkv + gk + Ec);   // Vh
        }
    };

    const int nkt = 2 * qt + 2;
    load_kv(0, 0);  CP_COMMIT();   // group: Q + KV0
    load_kv(1, 64); CP_COMMIT();   // nkt >= 2 always

    float o[8][4] = {};
    float mrow[2] = {-1e30f, -1e30f};
    float lsum[2] = {0.f, 0.f};

    int slot = 0;
    for (int kt = 0; kt < nkt; kt++) {
        int kc0 = kt * 64;
        CP_WAIT1();
        __syncthreads();

        if (kt + 2 < nkt) load_kv((kt + 2) % 3, (kt + 2) * 64);
        CP_COMMIT();

        __half* Kh = KV + slot * KVSTAGE;
        __half* Vh = Kh + FKV;
        slot = (slot == 2) ? 0 : slot + 1;

        if (kc0 <= warp_row_lo + 15) {
            bool domask = (kc0 + 63 > warp_row_lo);

            // ---- S = Q K^T (1-pass) ----
            float s[8][4] = {};
            #pragma unroll
            for (int ksj = 0; ksj < 4; ksj++) {
                int kk = ksj * 16 + lh8;
                uint32_t aq[4];
                ldm_x4(smem_u32(Qh + (wq * 16 + lrow) * LDH + kk), aq);
                #pragma unroll
                for (int nt = 0; nt < 4; nt++) {
                    uint32_t kh[4];
                    ldm_x4(smem_u32(Kh + (nt * 16 + lrow) * LDH + kk), kh);
                    mma_f16(s[2*nt+0], aq, kh[0], kh[2]);
                    mma_f16(s[2*nt+1], aq, kh[1], kh[3]);
                }
            }

            // ---- scale + causal mask ----
            int r_lo = warp_row_lo + (lane >> 2);
            #pragma unroll
            for (int n8 = 0; n8 < 8; n8++) {
                int c0 = kc0 + n8 * 8 + (lane & 3) * 2;
                #pragma unroll
                for (int cc = 0; cc < 4; cc++) {
                    float v = s[n8][cc] * 0.125f;
                    if (domask) {
                        int col = c0 + (cc & 1);
                        int row = r_lo + (cc >> 1) * 8;
                        if (col > row) v = -1e30f;
                    }
                    s[n8][cc] = v;
                }
            }

            // ---- online softmax ----
            #pragma unroll
            for (int hh = 0; hh < 2; hh++) {
                float tm = -1e30f;
                #pragma unroll
                for (int n8 = 0; n8 < 8; n8++)
                    tm = fmaxf(tm, fmaxf(s[n8][2*hh], s[n8][2*hh+1]));
                tm = fmaxf(tm, __shfl_xor_sync(0xffffffffu, tm, 1));
                tm = fmaxf(tm, __shfl_xor_sync(0xffffffffu, tm, 2));
                float mn = fmaxf(mrow[hh], tm);
                float corr = __expf(mrow[hh] - mn);
                mrow[hh] = mn;
                float rs = 0.f;
                #pragma unroll
                for (int n8 = 0; n8 < 8; n8++) {
                    s[n8][2*hh]   = __expf(s[n8][2*hh]   - mn);
                    s[n8][2*hh+1] = __expf(s[n8][2*hh+1] - mn);
                    rs += s[n8][2*hh] + s[n8][2*hh+1];
                }
                rs += __shfl_xor_sync(0xffffffffu, rs, 1);
                rs += __shfl_xor_sync(0xffffffffu, rs, 2);
                lsum[hh] = lsum[hh] * corr + rs;
                #pragma unroll
                for (int n8 = 0; n8 < 8; n8++) {
                    o[n8][2*hh]   *= corr;
                    o[n8][2*hh+1] *= corr;
                }
            }

            // ---- O += P V (1-pass) ----
            #pragma unroll
            for (int j = 0; j < 4; j++) {
                uint32_t pA[4];
                #pragma unroll
                for (int q2 = 0; q2 < 2; q2++) {
                    const float* sp = s[2*j + q2];
                    pA[q2*2 + 0] = pack_f2(sp[0], sp[1]);
                    pA[q2*2 + 1] = pack_f2(sp[2], sp[3]);
                }
                #pragma unroll
                for (int nt = 0; nt < 4; nt++) {
                    uint32_t vh[4];
                    ldm_x4_t(smem_u32(Vh + (j * 16 + lrow) * LDH + nt * 16 + lh8), vh);
                    mma_f16(o[2*nt+0], pA, vh[0], vh[1]);
                    mma_f16(o[2*nt+1], pA, vh[2], vh[3]);
                }
            }
        }
    }

    // ---- epilogue: normalize, round, write fp16 attn ----
    #pragma unroll
    for (int hh = 0; hh < 2; hh++) {
        float inv = 1.0f / lsum[hh];
        int row = warp_row_lo + (lane >> 2) + hh * 8;
        size_t base = (size_t)(b * Sc + row) * Ec + h * HDc;
        #pragma unroll
        for (int n8 = 0; n8 < 8; n8++) {
            int d = n8 * 8 + (lane & 3) * 2;
            *reinterpret_cast<uint32_t*>(g_attn16 + base + d) =
                pack_f2(o[n8][2*hh] * inv, o[n8][2*hh+1] * inv);
        }
    }
}

// ===========================================================================
extern "C" void kernel_launch(void* const* d_in, const int* in_sizes, int n_in,
                              void* d_out, int out_size)
{
    const float* x      = (const float*)d_in[0];
    const float* qkv_w  = (const float*)d_in[1];
    const float* qkv_b  = (const float*)d_in[2];
    const float* out_w  = (const float*)d_in[3];
    const float* out_b  = (const float*)d_in[4];
    float* out = (float*)d_out;

    __half *x16, *wq16, *wo16, *qkv16, *a16;
    cudaGetSymbolAddress((void**)&x16,   g_x16);
    cudaGetSymbolAddress((void**)&wq16,  g_wq16);
    cudaGetSymbolAddress((void**)&wo16,  g_wo16);
    cudaGetSymbolAddress((void**)&qkv16, g_qkv16);
    cudaGetSymbolAddress((void**)&a16,   g_attn16);

    cudaFuncSetAttribute(gemm_f16_kernel<true>,
                         cudaFuncAttributeMaxDynamicSharedMemorySize, GEMM_SMEM);
    cudaFuncSetAttribute(gemm_f16_kernel<false>,
                         cudaFuncAttributeMaxDynamicSharedMemorySize, GEMM_SMEM);
    cudaFuncSetAttribute(flash_tc_kernel,
                         cudaFuncAttributeMaxDynamicSharedMemorySize, FLASH_SMEM);

    // 0) prepass: one kernel rounds x + both weights
    round_all_kernel<<<(NALL4 + 255) / 256, 256>>>(x, qkv_w, out_w, x16, wq16, wo16);

    // 1) QKV projection (1-pass) -> fp16 qkv
    dim3 g1(E3 / 128, Mc / 128);   // (24, 32)
    gemm_f16_kernel<true><<<g1, 256, GEMM_SMEM>>>(x16, wq16, qkv_b, nullptr, qkv16, Mc, E3, Ec);

    // 2) Flash attention -> fp16 attn
    dim3 g2(Sc / 128, Hc, Bc);     // (16, 16, 2)
    flash_tc_kernel<<<g2, 256, FLASH_SMEM>>>(qkv16);

    // 3) Output projection (1-pass) -> fp32 out
    dim3 g3(Ec / 128, Mc / 128);   // (8, 32)
    gemm_f16_kernel<false><<<g3, 256, GEMM_SMEM>>>(a16, wo16, out_b, out, nullptr, Mc, Ec, Ec);
}